// round 1
// baseline (speedup 1.0000x reference)
#include <cuda_runtime.h>
#include <cstdint>
#include <cstddef>

#define THREADS 256

// Scratch activations (allocation-free): h0 [8192,2048], h2 [8192,2048]
__device__ float g_h0[8192u * 2048u];
__device__ float g_h2[8192u * 2048u];

// b-spline gaussian centers: (-0.02 + (j-3)*0.008), j=0..7, cast to f32
__constant__ float CENTERS[8] = {-0.044f, -0.036f, -0.028f, -0.02f,
                                 -0.012f, -0.004f,  0.004f,  0.012f};

// ---------------- threefry2x32 (JAX-compatible) ----------------
__device__ __forceinline__ uint32_t rotl32d(uint32_t v, int d) {
    return __funnelshift_l(v, v, d);
}

__device__ __forceinline__ void threefry2x32_dev(uint32_t k0, uint32_t k1,
                                                 uint32_t c0, uint32_t c1,
                                                 uint32_t& o0, uint32_t& o1) {
    uint32_t ks2 = k0 ^ k1 ^ 0x1BD11BDAu;
    uint32_t x0 = c0 + k0, x1 = c1 + k1;
#define TF_RND(r) { x0 += x1; x1 = rotl32d(x1, r); x1 ^= x0; }
    TF_RND(13) TF_RND(15) TF_RND(26) TF_RND(6)
    x0 += k1;  x1 += ks2 + 1u;
    TF_RND(17) TF_RND(29) TF_RND(16) TF_RND(24)
    x0 += ks2; x1 += k0 + 2u;
    TF_RND(13) TF_RND(15) TF_RND(26) TF_RND(6)
    x0 += k0;  x1 += k1 + 3u;
    TF_RND(17) TF_RND(29) TF_RND(16) TF_RND(24)
    x0 += k1;  x1 += ks2 + 4u;
    TF_RND(13) TF_RND(15) TF_RND(26) TF_RND(6)
    x0 += ks2; x1 += k0 + 5u;
#undef TF_RND
    o0 = x0; o1 = x1;
}

// Host copy for key fold_in
static inline uint32_t rotl32h(uint32_t v, int d) {
    return (v << d) | (v >> (32 - d));
}
static void threefry2x32_host(uint32_t k0, uint32_t k1, uint32_t c0, uint32_t c1,
                              uint32_t& o0, uint32_t& o1) {
    uint32_t ks2 = k0 ^ k1 ^ 0x1BD11BDAu;
    uint32_t x0 = c0 + k0, x1 = c1 + k1;
#define TF_RND(r) { x0 += x1; x1 = rotl32h(x1, r); x1 ^= x0; }
    TF_RND(13) TF_RND(15) TF_RND(26) TF_RND(6)
    x0 += k1;  x1 += ks2 + 1u;
    TF_RND(17) TF_RND(29) TF_RND(16) TF_RND(24)
    x0 += ks2; x1 += k0 + 2u;
    TF_RND(13) TF_RND(15) TF_RND(26) TF_RND(6)
    x0 += k0;  x1 += k1 + 3u;
    TF_RND(17) TF_RND(29) TF_RND(16) TF_RND(24)
    x0 += k1;  x1 += ks2 + 4u;
    TF_RND(13) TF_RND(15) TF_RND(26) TF_RND(6)
    x0 += ks2; x1 += k0 + 5u;
#undef TF_RND
    o0 = x0; o1 = x1;
}

// ---------------- fused KAN layer kernel ----------------
// out[b,o] = silu(x@bw)[b,o]*sb[o] + einsum(bases, sw)[b,o]*ss[o] + noise*sn
// Tile: 64x64 output, BK=8 input cols (-> 64 spline-K + 8 base-K per iter)
__global__ __launch_bounds__(THREADS)
void kan_layer_kernel(const float* __restrict__ x,
                      const float* __restrict__ sw,   // [I, O, 8]
                      const float* __restrict__ bw,   // [I, O]
                      const float* __restrict__ sb,   // [1, O]
                      const float* __restrict__ ss,   // [1, O]
                      const float* __restrict__ snp,  // scalar
                      float* __restrict__ out,        // [B, O]
                      int I, int O,
                      uint32_t nk0, uint32_t nk1) {
    __shared__ __align__(16) float xs[64][17];     // [m][i], 17-pad: conflict-free
    __shared__ __align__(16) float basesS[64][68]; // [kk=(i*8+g)][m]
    __shared__ __align__(16) float swS[64][68];    // [kk][o]
    __shared__ __align__(16) float bwS[8][68];     // [ki][o]

    const int tid = threadIdx.x;
    const int tx  = tid & 15;   // n-dim thread coord
    const int ty  = tid >> 4;   // m-dim thread coord
    const int m0  = blockIdx.y * 64;
    const int n0  = blockIdx.x * 64;

    float accS[4][4] = {};
    float accB[4][4] = {};

    for (int kb = 0; kb < I; kb += 8) {
        // x tile [64][8]
        #pragma unroll
        for (int r = 0; r < 2; ++r) {
            int idx = r * THREADS + tid;
            int m = idx >> 3, i = idx & 7;
            xs[m][i] = x[(size_t)(m0 + m) * I + kb + i];
        }
        // sw tile: for each local i, 512 contiguous floats (o,g) -> swS[ki*8+g][o]
        #pragma unroll
        for (int r = 0; r < 16; ++r) {
            int idx = r * THREADS + tid;
            int ki = idx >> 9;
            int rem = idx & 511;
            int o = rem >> 3, g = rem & 7;
            swS[ki * 8 + g][o] = sw[((size_t)(kb + ki) * O + (n0 + o)) * 8 + g];
        }
        // bw tile [8][64]
        #pragma unroll
        for (int r = 0; r < 2; ++r) {
            int idx = r * THREADS + tid;
            int ki = idx >> 6, o = idx & 63;
            bwS[ki][o] = bw[(size_t)(kb + ki) * O + n0 + o];
        }
        __syncthreads();

        // expand bases: exp(-0.5*((x - c_g)/0.4)^2)
        #pragma unroll
        for (int r = 0; r < 16; ++r) {
            int idx = r * THREADS + tid;
            int kk = idx >> 6, m = idx & 63;
            int i = kk >> 3, g = kk & 7;
            float t = (xs[m][i] - CENTERS[g]) * 2.5f;
            basesS[kk][m] = __expf(-0.5f * t * t);
        }
        __syncthreads();

        // spline GEMM: 64 k-steps
        #pragma unroll 16
        for (int kk = 0; kk < 64; ++kk) {
            float4 av = *reinterpret_cast<const float4*>(&basesS[kk][ty * 4]);
            float4 bv = *reinterpret_cast<const float4*>(&swS[kk][tx * 4]);
            float a[4] = {av.x, av.y, av.z, av.w};
            float bq[4] = {bv.x, bv.y, bv.z, bv.w};
            #pragma unroll
            for (int em = 0; em < 4; ++em)
                #pragma unroll
                for (int en = 0; en < 4; ++en)
                    accS[em][en] = fmaf(a[em], bq[en], accS[em][en]);
        }
        // base GEMM: 8 k-steps
        #pragma unroll
        for (int kk = 0; kk < 8; ++kk) {
            float a[4];
            #pragma unroll
            for (int em = 0; em < 4; ++em) a[em] = xs[ty * 4 + em][kk];
            float4 bv = *reinterpret_cast<const float4*>(&bwS[kk][tx * 4]);
            float bq[4] = {bv.x, bv.y, bv.z, bv.w};
            #pragma unroll
            for (int em = 0; em < 4; ++em)
                #pragma unroll
                for (int en = 0; en < 4; ++en)
                    accB[em][en] = fmaf(a[em], bq[en], accB[em][en]);
        }
        __syncthreads();
    }

    // epilogue: silu, scale, JAX-exact noise
    const float snv = *snp;
    #pragma unroll
    for (int em = 0; em < 4; ++em) {
        int b = m0 + ty * 4 + em;
        #pragma unroll
        for (int en = 0; en < 4; ++en) {
            int o = n0 + tx * 4 + en;
            float bg = accB[em][en];
            float sg = 1.0f / (1.0f + expf(-bg));
            float base = bg * sg;

            // jax.random.normal (threefry, partitionable): bits = o0^o1 of
            // threefry(key, (0, linear_index))
            uint32_t li = (uint32_t)b * (uint32_t)O + (uint32_t)o;
            uint32_t r0, r1;
            threefry2x32_dev(nk0, nk1, 0u, li, r0, r1);
            uint32_t bits = r0 ^ r1;
            float f = __uint_as_float((bits >> 9) | 0x3f800000u) - 1.0f;
            float u = fmaxf(-0.99999994f, fmaf(f, 2.0f, -0.99999994f));
            float nz = 1.41421356f * erfinvf(u);

            out[(size_t)b * O + o] = base * sb[o] + accS[em][en] * ss[o] + nz * snv;
        }
    }
}

// ---------------- launch ----------------
extern "C" void kernel_launch(void* const* d_in, const int* in_sizes, int n_in,
                              void* d_out, int out_size) {
    const float* x = (const float*)d_in[0];
    const float* sw[4]; const float* bw[4]; const float* sb[4];
    const float* ss[4]; const float* sn[4];
    for (int li = 0; li < 4; ++li) {
        sw[li] = (const float*)d_in[1 + 5 * li + 0];
        bw[li] = (const float*)d_in[1 + 5 * li + 1];
        sb[li] = (const float*)d_in[1 + 5 * li + 2];
        ss[li] = (const float*)d_in[1 + 5 * li + 3];
        sn[li] = (const float*)d_in[1 + 5 * li + 4];
    }
    const int B = in_sizes[0] / 1024;   // 8192
    float* out  = (float*)d_out;
    float* xrec = out;                       // [B, 1024]
    float* z    = out + (size_t)B * 1024;    // [B, 256]

    float* h0; cudaGetSymbolAddress((void**)&h0, g_h0);
    float* h2; cudaGetSymbolAddress((void**)&h2, g_h2);

    // noise keys: nk = key(42) = [0,42]; fold_in(nk, li) = threefry(nk, (0, li))
    uint32_t fk0[4], fk1[4];
    for (int li = 0; li < 4; ++li)
        threefry2x32_host(0u, 42u, 0u, (uint32_t)li, fk0[li], fk1[li]);

    dim3 blk(THREADS);
    {   // L0: 1024 -> 2048, out h0
        dim3 g(2048 / 64, B / 64);
        kan_layer_kernel<<<g, blk>>>(x, sw[0], bw[0], sb[0], ss[0], sn[0],
                                     h0, 1024, 2048, fk0[0], fk1[0]);
    }
    {   // L1: 2048 -> 256, out z (second output)
        dim3 g(256 / 64, B / 64);
        kan_layer_kernel<<<g, blk>>>(h0, sw[1], bw[1], sb[1], ss[1], sn[1],
                                     z, 2048, 256, fk0[1], fk1[1]);
    }
    {   // L2: 256 -> 2048, out h2
        dim3 g(2048 / 64, B / 64);
        kan_layer_kernel<<<g, blk>>>(z, sw[2], bw[2], sb[2], ss[2], sn[2],
                                     h2, 256, 2048, fk0[2], fk1[2]);
    }
    {   // L3: 2048 -> 1024, out x_rec (first output)
        dim3 g(1024 / 64, B / 64);
        kan_layer_kernel<<<g, blk>>>(h2, sw[3], bw[3], sb[3], ss[3], sn[3],
                                     xrec, 2048, 1024, fk0[3], fk1[3]);
    }
}

// round 3
// speedup vs baseline: 2.3874x; 2.3874x over previous
#include <cuda_runtime.h>
#include <cuda_bf16.h>
#include <cstdint>
#include <cstddef>

#define THREADS 256

// Scratch activations (allocation-free): h0 [8192,2048], h2 [8192,2048]
__device__ float g_h0[8192u * 2048u];
__device__ float g_h2[8192u * 2048u];

// Gaussian basis recurrence: e_g = e0 * u^g * exp(-2e-4*g^2)
// d = x + 0.044; e0 = exp(-3.125 d^2); u = exp(0.05 d)
__constant__ float RAT[7] = {0.99980002f, 0.99940018f, 0.99900050f,
                             0.99860098f, 0.99820162f, 0.99780242f, 0.99740338f};

// ---------------- threefry2x32 (JAX-compatible, validated R1) ----------------
__device__ __forceinline__ uint32_t rotl32d(uint32_t v, int d) {
    return __funnelshift_l(v, v, d);
}
__device__ __forceinline__ void threefry2x32_dev(uint32_t k0, uint32_t k1,
                                                 uint32_t c0, uint32_t c1,
                                                 uint32_t& o0, uint32_t& o1) {
    uint32_t ks2 = k0 ^ k1 ^ 0x1BD11BDAu;
    uint32_t x0 = c0 + k0, x1 = c1 + k1;
#define TF_RND(r) { x0 += x1; x1 = rotl32d(x1, r); x1 ^= x0; }
    TF_RND(13) TF_RND(15) TF_RND(26) TF_RND(6)
    x0 += k1;  x1 += ks2 + 1u;
    TF_RND(17) TF_RND(29) TF_RND(16) TF_RND(24)
    x0 += ks2; x1 += k0 + 2u;
    TF_RND(13) TF_RND(15) TF_RND(26) TF_RND(6)
    x0 += k0;  x1 += k1 + 3u;
    TF_RND(17) TF_RND(29) TF_RND(16) TF_RND(24)
    x0 += k1;  x1 += ks2 + 4u;
    TF_RND(13) TF_RND(15) TF_RND(26) TF_RND(6)
    x0 += ks2; x1 += k0 + 5u;
#undef TF_RND
    o0 = x0; o1 = x1;
}
static inline uint32_t rotl32h(uint32_t v, int d) {
    return (v << d) | (v >> (32 - d));
}
static void threefry2x32_host(uint32_t k0, uint32_t k1, uint32_t c0, uint32_t c1,
                              uint32_t& o0, uint32_t& o1) {
    uint32_t ks2 = k0 ^ k1 ^ 0x1BD11BDAu;
    uint32_t x0 = c0 + k0, x1 = c1 + k1;
#define TF_RND(r) { x0 += x1; x1 = rotl32h(x1, r); x1 ^= x0; }
    TF_RND(13) TF_RND(15) TF_RND(26) TF_RND(6)
    x0 += k1;  x1 += ks2 + 1u;
    TF_RND(17) TF_RND(29) TF_RND(16) TF_RND(24)
    x0 += ks2; x1 += k0 + 2u;
    TF_RND(13) TF_RND(15) TF_RND(26) TF_RND(6)
    x0 += k0;  x1 += k1 + 3u;
    TF_RND(17) TF_RND(29) TF_RND(16) TF_RND(24)
    x0 += k1;  x1 += ks2 + 4u;
    TF_RND(13) TF_RND(15) TF_RND(26) TF_RND(6)
    x0 += ks2; x1 += k0 + 5u;
#undef TF_RND
    o0 = x0; o1 = x1;
}

// ---------------- helpers ----------------
__device__ __forceinline__ uint32_t smem_u32(const void* p) {
    uint32_t a;
    asm("{ .reg .u64 t; cvta.to.shared.u64 t, %1; cvt.u32.u64 %0, t; }"
        : "=r"(a) : "l"(p));
    return a;
}
#define SW128(o) ((o) ^ ((((uint32_t)(o)) >> 3) & 0x70))

#define LDSM4(rv, a) \
    asm volatile("ldmatrix.sync.aligned.m8n8.x4.shared.b16 {%0,%1,%2,%3}, [%4];" \
        : "=r"((rv)[0]), "=r"((rv)[1]), "=r"((rv)[2]), "=r"((rv)[3]) \
        : "r"(a))

#define MMA_BF16(c, a, b0, b1) \
    asm volatile("mma.sync.aligned.m16n8k16.row.col.f32.bf16.bf16.f32 " \
        "{%0,%1,%2,%3}, {%4,%5,%6,%7}, {%8,%9}, {%0,%1,%2,%3};" \
        : "+f"((c)[0]), "+f"((c)[1]), "+f"((c)[2]), "+f"((c)[3]) \
        : "r"((a)[0]), "r"((a)[1]), "r"((a)[2]), "r"((a)[3]), "r"(b0), "r"(b1))

// bf16 hi/lo split of a float pair -> packed bf16x2 words
__device__ __forceinline__ void bfsplit2(float a, float b, uint32_t& hi2, uint32_t& lo2) {
    asm("cvt.rn.bf16x2.f32 %0, %1, %2;" : "=r"(hi2) : "f"(b), "f"(a));
    __nv_bfloat162 hv = *reinterpret_cast<__nv_bfloat162*>(&hi2);
    float ra = a - __bfloat162float(hv.x);
    float rb = b - __bfloat162float(hv.y);
    asm("cvt.rn.bf16x2.f32 %0, %1, %2;" : "=r"(lo2) : "f"(rb), "f"(ra));
}

// ---------------- SMEM layout (offsets from 1024-aligned base) ----------------
// bf16 tiles [rows][64 k] K-major, 128B rows, SW128
static constexpr int A_SP_HI = 0;
static constexpr int A_SP_LO = 16384;
static constexpr int B_SP_HI = 32768;
static constexpr int B_SP_LO = 49152;
static constexpr int A_BA_HI = 65536;
static constexpr int A_BA_LO = 81920;
static constexpr int B_BA_HI = 98304;
static constexpr int B_BA_LO = 114688;
static constexpr int XS_F32  = 131072;   // x fp32 [128][68]
static constexpr int SMEM_SZ = 131072 + 34816;
static constexpr int SMEM_DYN = SMEM_SZ + 1024;

// ---------------- fused KAN layer: mma.sync bf16x3 ----------------
__global__ __launch_bounds__(THREADS, 1)
void kan_mma_kernel(const float* __restrict__ x,
                    const float* __restrict__ sw,   // [I, O, 8]
                    const float* __restrict__ bw,   // [I, O]
                    const float* __restrict__ sbp,  // [1, O]
                    const float* __restrict__ ssp,  // [1, O]
                    const float* __restrict__ snp,  // scalar
                    float* __restrict__ out,        // [B, O]
                    int I, int O,
                    uint32_t nk0, uint32_t nk1) {
    extern __shared__ char raw[];
    const uint32_t rawu = smem_u32(raw);
    const uint32_t sbase = (rawu + 1023u) & ~1023u;
    char* smb = raw + (sbase - rawu);
    float* xs = reinterpret_cast<float*>(smb + XS_F32);

    const int tid = threadIdx.x;
    const int wid = tid >> 5;
    const int lid = tid & 31;
    const int wm  = wid >> 2;       // 0..1
    const int wn  = wid & 3;        // 0..3
    const int m0  = blockIdx.x * 128;   // m fastest (L2 reuse of sw)
    const int n0  = blockIdx.y * 128;

    // ldmatrix per-lane geometry
    const int q = lid >> 3, r = lid & 7;
    const int rowA_l = r + (q & 1) * 8;        // A: row within m16
    const int kselA  = (q >> 1) * 16;          // A: +16B for k8..15 matrices
    const int rowB_l = r + (q >> 1) * 8;       // B: row within n16
    const int kselB  = (q & 1) * 16;

    float accS[4][4][4];   // [mf][nf][e]
    float accB[4][4][4];
    #pragma unroll
    for (int a = 0; a < 4; ++a)
        #pragma unroll
        for (int b = 0; b < 4; ++b)
            #pragma unroll
            for (int e = 0; e < 4; ++e) { accS[a][b][e] = 0.f; accB[a][b][e] = 0.f; }

    const uint32_t AspH = sbase + A_SP_HI, AspL = sbase + A_SP_LO;
    const uint32_t BspH = sbase + B_SP_HI, BspL = sbase + B_SP_LO;
    const uint32_t AbaH = sbase + A_BA_HI, AbaL = sbase + A_BA_LO;
    const uint32_t BbaH = sbase + B_BA_HI, BbaL = sbase + B_BA_LO;

    for (int kb = 0; kb < I; kb += 64) {
        // ---- big-chunk fill: x fp32 + A_base hi/lo ----
        #pragma unroll
        for (int rr = 0; rr < 8; ++rr) {
            int v = rr * THREADS + tid;         // 2048 float4 tasks
            int m = v >> 4, c4 = v & 15;
            float4 xv = *reinterpret_cast<const float4*>(
                &x[(size_t)(m0 + m) * I + kb + c4 * 4]);
            *reinterpret_cast<float4*>(&xs[m * 68 + c4 * 4]) = xv;
            uint32_t h0w, l0w, h1w, l1w;
            bfsplit2(xv.x, xv.y, h0w, l0w);
            bfsplit2(xv.z, xv.w, h1w, l1w);
            uint32_t off = SW128((uint32_t)(m * 128 + c4 * 8));
            *reinterpret_cast<uint2*>(smb + A_BA_HI + off) = make_uint2(h0w, h1w);
            *reinterpret_cast<uint2*>(smb + A_BA_LO + off) = make_uint2(l0w, l1w);
        }
        // ---- B_base fill: bw -> [n][k] hi/lo ----
        #pragma unroll
        for (int rr = 0; rr < 16; ++rr) {
            int v = rr * THREADS + tid;         // 4096 k-pair tasks
            int kp = v >> 7, n = v & 127;
            float b0 = bw[(size_t)(kb + 2 * kp) * O + n0 + n];
            float b1 = bw[(size_t)(kb + 2 * kp + 1) * O + n0 + n];
            uint32_t hw, lw;
            bfsplit2(b0, b1, hw, lw);
            uint32_t off = SW128((uint32_t)(n * 128 + kp * 4));
            *reinterpret_cast<uint32_t*>(smb + B_BA_HI + off) = hw;
            *reinterpret_cast<uint32_t*>(smb + B_BA_LO + off) = lw;
        }
        __syncthreads();

        for (int sub = 0; sub < 8; ++sub) {
            // ---- A_spline fill: basis recurrence ----
            #pragma unroll
            for (int rr = 0; rr < 4; ++rr) {
                int t = rr * THREADS + tid;      // 1024 (m,i) tasks
                int m = t >> 3, il = t & 7;
                float xv = xs[m * 68 + sub * 8 + il];
                float d = xv + 0.044f;
                float e = __expf(-3.125f * d * d);
                float u = __expf(0.05f * d);
                float v[8];
                v[0] = e;
                #pragma unroll
                for (int g = 1; g < 8; ++g) v[g] = v[g - 1] * u * RAT[g - 1];
                uint32_t hw[4], lw[4];
                #pragma unroll
                for (int qq = 0; qq < 4; ++qq)
                    bfsplit2(v[2 * qq], v[2 * qq + 1], hw[qq], lw[qq]);
                uint32_t off = SW128((uint32_t)(m * 128 + il * 16));
                *reinterpret_cast<uint4*>(smb + A_SP_HI + off) =
                    make_uint4(hw[0], hw[1], hw[2], hw[3]);
                *reinterpret_cast<uint4*>(smb + A_SP_LO + off) =
                    make_uint4(lw[0], lw[1], lw[2], lw[3]);
            }
            // ---- B_spline fill: sw[(kb+sub*8+ii), n0+n, g] -> [n][kk] ----
            #pragma unroll
            for (int rr = 0; rr < 16; ++rr) {
                int p = rr * THREADS + tid;      // 4096 g-pair tasks
                int ii = p >> 9, rem = p & 511;
                int n = rem >> 2, g2 = (rem & 3) * 2;
                float2 wv = *reinterpret_cast<const float2*>(
                    &sw[((size_t)(kb + sub * 8 + ii) * O + (n0 + n)) * 8 + g2]);
                uint32_t hw, lw;
                bfsplit2(wv.x, wv.y, hw, lw);
                uint32_t off = SW128((uint32_t)(n * 128 + ii * 16 + g2 * 2));
                *reinterpret_cast<uint32_t*>(smb + B_SP_HI + off) = hw;
                *reinterpret_cast<uint32_t*>(smb + B_SP_LO + off) = lw;
            }
            __syncthreads();

            // ---- spline MMA: K=64 = 4 k16 steps, 3 products ----
            #pragma unroll
            for (int k16 = 0; k16 < 4; ++k16) {
                const int kbyt = k16 * 32;
                uint32_t ah[4][4], al[4][4];
                #pragma unroll
                for (int mf = 0; mf < 4; ++mf) {
                    int m = wm * 64 + mf * 16 + rowA_l;
                    uint32_t off = (uint32_t)(m * 128)
                                 + (((uint32_t)(kbyt + kselA)) ^ ((m * 16) & 0x70));
                    LDSM4(ah[mf], AspH + off);
                    LDSM4(al[mf], AspL + off);
                }
                uint32_t bh[2][4], bl[2][4];
                #pragma unroll
                for (int nb = 0; nb < 2; ++nb) {
                    int n = wn * 32 + nb * 16 + rowB_l;
                    uint32_t off = (uint32_t)(n * 128)
                                 + (((uint32_t)(kbyt + kselB)) ^ ((n * 16) & 0x70));
                    LDSM4(bh[nb], BspH + off);
                    LDSM4(bl[nb], BspL + off);
                }
                #pragma unroll
                for (int mf = 0; mf < 4; ++mf)
                    #pragma unroll
                    for (int nf = 0; nf < 4; ++nf) {
                        const int nb = nf >> 1, ri = (nf & 1) * 2;
                        MMA_BF16(accS[mf][nf], ah[mf], bh[nb][ri], bh[nb][ri + 1]);
                        MMA_BF16(accS[mf][nf], ah[mf], bl[nb][ri], bl[nb][ri + 1]);
                        MMA_BF16(accS[mf][nf], al[mf], bh[nb][ri], bh[nb][ri + 1]);
                    }
            }

            // ---- base MMA: once per big-chunk ----
            if (sub == 0) {
                #pragma unroll
                for (int k16 = 0; k16 < 4; ++k16) {
                    const int kbyt = k16 * 32;
                    uint32_t ah[4][4], al[4][4];
                    #pragma unroll
                    for (int mf = 0; mf < 4; ++mf) {
                        int m = wm * 64 + mf * 16 + rowA_l;
                        uint32_t off = (uint32_t)(m * 128)
                                     + (((uint32_t)(kbyt + kselA)) ^ ((m * 16) & 0x70));
                        LDSM4(ah[mf], AbaH + off);
                        LDSM4(al[mf], AbaL + off);
                    }
                    uint32_t bh[2][4], bl[2][4];
                    #pragma unroll
                    for (int nb = 0; nb < 2; ++nb) {
                        int n = wn * 32 + nb * 16 + rowB_l;
                        uint32_t off = (uint32_t)(n * 128)
                                     + (((uint32_t)(kbyt + kselB)) ^ ((n * 16) & 0x70));
                        LDSM4(bh[nb], BbaH + off);
                        LDSM4(bl[nb], BbaL + off);
                    }
                    #pragma unroll
                    for (int mf = 0; mf < 4; ++mf)
                        #pragma unroll
                        for (int nf = 0; nf < 4; ++nf) {
                            const int nb = nf >> 1, ri = (nf & 1) * 2;
                            MMA_BF16(accB[mf][nf], ah[mf], bh[nb][ri], bh[nb][ri + 1]);
                            MMA_BF16(accB[mf][nf], ah[mf], bl[nb][ri], bl[nb][ri + 1]);
                            MMA_BF16(accB[mf][nf], al[mf], bh[nb][ri], bh[nb][ri + 1]);
                        }
                }
            }
            __syncthreads();
        }
    }

    // ---------------- epilogue ----------------
    const float snv = *snp;
    const int rq = lid >> 2, cq = (lid & 3) * 2;
    #pragma unroll
    for (int mf = 0; mf < 4; ++mf) {
        #pragma unroll
        for (int nf = 0; nf < 4; ++nf) {
            #pragma unroll
            for (int half = 0; half < 2; ++half) {
                int b = m0 + wm * 64 + mf * 16 + rq + half * 8;
                int obase = n0 + wn * 32 + nf * 8 + cq;
                float2 res;
                #pragma unroll
                for (int e = 0; e < 2; ++e) {
                    int o = obase + e;
                    float sv = accS[mf][nf][half * 2 + e];
                    float bv = accB[mf][nf][half * 2 + e];
                    float sg = 1.0f / (1.0f + __expf(-bv));
                    uint32_t li = (uint32_t)b * (uint32_t)O + (uint32_t)o;
                    uint32_t r0, r1;
                    threefry2x32_dev(nk0, nk1, 0u, li, r0, r1);
                    uint32_t bits = r0 ^ r1;
                    float f = __uint_as_float((bits >> 9) | 0x3f800000u) - 1.0f;
                    float uu = fmaxf(-0.99999994f, fmaf(f, 2.0f, -0.99999994f));
                    float nz = 1.41421356f * erfinvf(uu);
                    float val = bv * sg * sbp[o] + sv * ssp[o] + nz * snv;
                    if (e == 0) res.x = val; else res.y = val;
                }
                *reinterpret_cast<float2*>(&out[(size_t)b * O + obase]) = res;
            }
        }
    }
}

// ---------------- launch ----------------
extern "C" void kernel_launch(void* const* d_in, const int* in_sizes, int n_in,
                              void* d_out, int out_size) {
    const float* x = (const float*)d_in[0];
    const float* sw[4]; const float* bw[4]; const float* sb[4];
    const float* ss[4]; const float* sn[4];
    for (int li = 0; li < 4; ++li) {
        sw[li] = (const float*)d_in[1 + 5 * li + 0];
        bw[li] = (const float*)d_in[1 + 5 * li + 1];
        sb[li] = (const float*)d_in[1 + 5 * li + 2];
        ss[li] = (const float*)d_in[1 + 5 * li + 3];
        sn[li] = (const float*)d_in[1 + 5 * li + 4];
    }
    const int B = in_sizes[0] / 1024;   // 8192
    float* out  = (float*)d_out;
    float* xrec = out;                       // [B, 1024]
    float* z    = out + (size_t)B * 1024;    // [B, 256]

    float* h0; cudaGetSymbolAddress((void**)&h0, g_h0);
    float* h2; cudaGetSymbolAddress((void**)&h2, g_h2);

    uint32_t fk0[4], fk1[4];
    for (int li = 0; li < 4; ++li)
        threefry2x32_host(0u, 42u, 0u, (uint32_t)li, fk0[li], fk1[li]);

    cudaFuncSetAttribute(kan_mma_kernel,
                         cudaFuncAttributeMaxDynamicSharedMemorySize, SMEM_DYN);

    dim3 blk(THREADS);
    {   // L0: 1024 -> 2048
        dim3 g(B / 128, 2048 / 128);
        kan_mma_kernel<<<g, blk, SMEM_DYN>>>(x, sw[0], bw[0], sb[0], ss[0], sn[0],
                                             h0, 1024, 2048, fk0[0], fk1[0]);
    }
    {   // L1: 2048 -> 256 (z output)
        dim3 g(B / 128, 256 / 128);
        kan_mma_kernel<<<g, blk, SMEM_DYN>>>(h0, sw[1], bw[1], sb[1], ss[1], sn[1],
                                             z, 2048, 256, fk0[1], fk1[1]);
    }
    {   // L2: 256 -> 2048
        dim3 g(B / 128, 2048 / 128);
        kan_mma_kernel<<<g, blk, SMEM_DYN>>>(z, sw[2], bw[2], sb[2], ss[2], sn[2],
                                             h2, 256, 2048, fk0[2], fk1[2]);
    }
    {   // L3: 2048 -> 1024 (x_rec output)
        dim3 g(B / 128, 1024 / 128);
        kan_mma_kernel<<<g, blk, SMEM_DYN>>>(h2, sw[3], bw[3], sb[3], ss[3], sn[3],
                                             xrec, 2048, 1024, fk0[3], fk1[3]);
    }
}

// round 4
// speedup vs baseline: 2.4279x; 1.0170x over previous
#include <cuda_runtime.h>
#include <cuda_bf16.h>
#include <cstdint>
#include <cstddef>

#define THREADS 256

// Scratch activations (allocation-free): h0 [8192,2048], h2 [8192,2048]
__device__ float g_h0[8192u * 2048u];
__device__ float g_h2[8192u * 2048u];

// Gaussian basis recurrence: e_g = e0 * u^g * exp(-2e-4*g^2)
// d = x + 0.044; e0 = exp(-3.125 d^2); u = exp(0.05 d)
__constant__ float RAT[7] = {0.99980002f, 0.99940018f, 0.99900050f,
                             0.99860098f, 0.99820162f, 0.99780242f, 0.99740338f};

// ---------------- threefry2x32 (JAX-compatible, validated R1/R3) ----------------
__device__ __forceinline__ uint32_t rotl32d(uint32_t v, int d) {
    return __funnelshift_l(v, v, d);
}
__device__ __forceinline__ void threefry2x32_dev(uint32_t k0, uint32_t k1,
                                                 uint32_t c0, uint32_t c1,
                                                 uint32_t& o0, uint32_t& o1) {
    uint32_t ks2 = k0 ^ k1 ^ 0x1BD11BDAu;
    uint32_t x0 = c0 + k0, x1 = c1 + k1;
#define TF_RND(r) { x0 += x1; x1 = rotl32d(x1, r); x1 ^= x0; }
    TF_RND(13) TF_RND(15) TF_RND(26) TF_RND(6)
    x0 += k1;  x1 += ks2 + 1u;
    TF_RND(17) TF_RND(29) TF_RND(16) TF_RND(24)
    x0 += ks2; x1 += k0 + 2u;
    TF_RND(13) TF_RND(15) TF_RND(26) TF_RND(6)
    x0 += k0;  x1 += k1 + 3u;
    TF_RND(17) TF_RND(29) TF_RND(16) TF_RND(24)
    x0 += k1;  x1 += ks2 + 4u;
    TF_RND(13) TF_RND(15) TF_RND(26) TF_RND(6)
    x0 += ks2; x1 += k0 + 5u;
#undef TF_RND
    o0 = x0; o1 = x1;
}
static inline uint32_t rotl32h(uint32_t v, int d) {
    return (v << d) | (v >> (32 - d));
}
static void threefry2x32_host(uint32_t k0, uint32_t k1, uint32_t c0, uint32_t c1,
                              uint32_t& o0, uint32_t& o1) {
    uint32_t ks2 = k0 ^ k1 ^ 0x1BD11BDAu;
    uint32_t x0 = c0 + k0, x1 = c1 + k1;
#define TF_RND(r) { x0 += x1; x1 = rotl32h(x1, r); x1 ^= x0; }
    TF_RND(13) TF_RND(15) TF_RND(26) TF_RND(6)
    x0 += k1;  x1 += ks2 + 1u;
    TF_RND(17) TF_RND(29) TF_RND(16) TF_RND(24)
    x0 += ks2; x1 += k0 + 2u;
    TF_RND(13) TF_RND(15) TF_RND(26) TF_RND(6)
    x0 += k0;  x1 += k1 + 3u;
    TF_RND(17) TF_RND(29) TF_RND(16) TF_RND(24)
    x0 += k1;  x1 += ks2 + 4u;
    TF_RND(13) TF_RND(15) TF_RND(26) TF_RND(6)
    x0 += ks2; x1 += k0 + 5u;
#undef TF_RND
    o0 = x0; o1 = x1;
}

// ---------------- helpers ----------------
__device__ __forceinline__ uint32_t smem_u32(const void* p) {
    uint32_t a;
    asm("{ .reg .u64 t; cvta.to.shared.u64 t, %1; cvt.u32.u64 %0, t; }"
        : "=r"(a) : "l"(p));
    return a;
}
#define SW128(o) ((o) ^ ((((uint32_t)(o)) >> 3) & 0x70))

#define LDSM4(rv, a) \
    asm volatile("ldmatrix.sync.aligned.m8n8.x4.shared.b16 {%0,%1,%2,%3}, [%4];" \
        : "=r"((rv)[0]), "=r"((rv)[1]), "=r"((rv)[2]), "=r"((rv)[3]) \
        : "r"(a))

#define MMA_BF16(c, a, b0, b1) \
    asm volatile("mma.sync.aligned.m16n8k16.row.col.f32.bf16.bf16.f32 " \
        "{%0,%1,%2,%3}, {%4,%5,%6,%7}, {%8,%9}, {%0,%1,%2,%3};" \
        : "+f"((c)[0]), "+f"((c)[1]), "+f"((c)[2]), "+f"((c)[3]) \
        : "r"((a)[0]), "r"((a)[1]), "r"((a)[2]), "r"((a)[3]), "r"(b0), "r"(b1))

// bf16 hi/lo split of a float pair -> packed bf16x2 words
__device__ __forceinline__ void bfsplit2(float a, float b, uint32_t& hi2, uint32_t& lo2) {
    asm("cvt.rn.bf16x2.f32 %0, %1, %2;" : "=r"(hi2) : "f"(b), "f"(a));
    __nv_bfloat162 hv = *reinterpret_cast<__nv_bfloat162*>(&hi2);
    float ra = a - __bfloat162float(hv.x);
    float rb = b - __bfloat162float(hv.y);
    asm("cvt.rn.bf16x2.f32 %0, %1, %2;" : "=r"(lo2) : "f"(rb), "f"(ra));
}

// ---------------- SMEM layout (offsets from 1024-aligned base) ----------------
// Spline tiles double-buffered: buffer stride 64KB, each buffer holds
// A_hi/A_lo/B_hi/B_lo at +0/+16K/+32K/+48K. Base tiles single-buffered.
static constexpr int SP_BUF_STRIDE = 65536;
static constexpr int SP_A_HI = 0;
static constexpr int SP_A_LO = 16384;
static constexpr int SP_B_HI = 32768;
static constexpr int SP_B_LO = 49152;
static constexpr int A_BA_HI = 131072;
static constexpr int A_BA_LO = 147456;
static constexpr int B_BA_HI = 163840;
static constexpr int B_BA_LO = 180224;
static constexpr int SMEM_SZ = 196608;           // 192KB
static constexpr int SMEM_DYN = SMEM_SZ + 1024;

// ---------------- fused KAN layer: mma.sync bf16x3, double-buffered ----------------
__global__ __launch_bounds__(THREADS, 1)
void kan_mma_kernel(const float* __restrict__ x,
                    const float* __restrict__ sw,   // [I, O, 8]
                    const float* __restrict__ bw,   // [I, O]
                    const float* __restrict__ sbp,  // [1, O]
                    const float* __restrict__ ssp,  // [1, O]
                    const float* __restrict__ snp,  // scalar
                    float* __restrict__ out,        // [B, O]
                    int I, int O,
                    uint32_t nk0, uint32_t nk1) {
    extern __shared__ char raw[];
    const uint32_t rawu = smem_u32(raw);
    const uint32_t sbase = (rawu + 1023u) & ~1023u;
    char* smb = raw + (sbase - rawu);

    const int tid = threadIdx.x;
    const int wid = tid >> 5;
    const int lid = tid & 31;
    const int wm  = wid >> 2;       // 0..1
    const int wn  = wid & 3;        // 0..3
    const int m0  = blockIdx.x * 128;   // m fastest (L2 reuse of sw)
    const int n0  = blockIdx.y * 128;

    // ldmatrix per-lane geometry
    const int q = lid >> 3, r = lid & 7;
    const int rowA_l = r + (q & 1) * 8;
    const int kselA  = (q >> 1) * 16;
    const int rowB_l = r + (q >> 1) * 8;
    const int kselB  = (q & 1) * 16;

    float accS[4][4][4];
    float accB[4][4][4];
    #pragma unroll
    for (int a = 0; a < 4; ++a)
        #pragma unroll
        for (int b = 0; b < 4; ++b)
            #pragma unroll
            for (int e = 0; e < 4; ++e) { accS[a][b][e] = 0.f; accB[a][b][e] = 0.f; }

    // ---- fill one spline sub-chunk buffer (basis recurrence + sw convert) ----
    auto fill_spline = [&](int buf, int kb, int sub) {
        char* bA_hi = smb + buf * SP_BUF_STRIDE + SP_A_HI;
        char* bA_lo = smb + buf * SP_BUF_STRIDE + SP_A_LO;
        char* bB_hi = smb + buf * SP_BUF_STRIDE + SP_B_HI;
        char* bB_lo = smb + buf * SP_BUF_STRIDE + SP_B_LO;
        // basis: 1024 (m, il) tasks; x reconstructed from base-A hi+lo tiles
        #pragma unroll
        for (int rr = 0; rr < 4; ++rr) {
            int t = rr * THREADS + tid;
            int m = t >> 3, il = t & 7;
            uint32_t xoff = SW128((uint32_t)(m * 128 + (sub * 8 + il) * 2));
            float xh = __bfloat162float(
                *reinterpret_cast<const __nv_bfloat16*>(smb + A_BA_HI + xoff));
            float xl = __bfloat162float(
                *reinterpret_cast<const __nv_bfloat16*>(smb + A_BA_LO + xoff));
            float xv = xh + xl;
            float d = xv + 0.044f;
            float e = __expf(-3.125f * d * d);
            float u = __expf(0.05f * d);
            float v[8];
            v[0] = e;
            #pragma unroll
            for (int g = 1; g < 8; ++g) v[g] = v[g - 1] * u * RAT[g - 1];
            uint32_t hw[4], lw[4];
            #pragma unroll
            for (int qq = 0; qq < 4; ++qq)
                bfsplit2(v[2 * qq], v[2 * qq + 1], hw[qq], lw[qq]);
            uint32_t off = SW128((uint32_t)(m * 128 + il * 16));
            *reinterpret_cast<uint4*>(bA_hi + off) = make_uint4(hw[0], hw[1], hw[2], hw[3]);
            *reinterpret_cast<uint4*>(bA_lo + off) = make_uint4(lw[0], lw[1], lw[2], lw[3]);
        }
        // sw: 4096 g-pair tasks
        #pragma unroll
        for (int rr = 0; rr < 16; ++rr) {
            int p = rr * THREADS + tid;
            int ii = p >> 9, rem = p & 511;
            int n = rem >> 2, g2 = (rem & 3) * 2;
            float2 wv = *reinterpret_cast<const float2*>(
                &sw[((size_t)(kb + sub * 8 + ii) * O + (n0 + n)) * 8 + g2]);
            uint32_t hw, lw;
            bfsplit2(wv.x, wv.y, hw, lw);
            uint32_t off = SW128((uint32_t)(n * 128 + ii * 16 + g2 * 2));
            *reinterpret_cast<uint32_t*>(bB_hi + off) = hw;
            *reinterpret_cast<uint32_t*>(bB_lo + off) = lw;
        }
    };

    // ---- MMA over one spline buffer ----
    auto mma_spline = [&](int buf) {
        const uint32_t Ah = sbase + buf * SP_BUF_STRIDE + SP_A_HI;
        const uint32_t Al = sbase + buf * SP_BUF_STRIDE + SP_A_LO;
        const uint32_t Bh = sbase + buf * SP_BUF_STRIDE + SP_B_HI;
        const uint32_t Bl = sbase + buf * SP_BUF_STRIDE + SP_B_LO;
        #pragma unroll
        for (int k16 = 0; k16 < 4; ++k16) {
            const int kbyt = k16 * 32;
            uint32_t ah[4][4], al[4][4];
            #pragma unroll
            for (int mf = 0; mf < 4; ++mf) {
                int m = wm * 64 + mf * 16 + rowA_l;
                uint32_t off = (uint32_t)(m * 128)
                             + (((uint32_t)(kbyt + kselA)) ^ ((m * 16) & 0x70));
                LDSM4(ah[mf], Ah + off);
                LDSM4(al[mf], Al + off);
            }
            uint32_t bh[2][4], bl[2][4];
            #pragma unroll
            for (int nb = 0; nb < 2; ++nb) {
                int n = wn * 32 + nb * 16 + rowB_l;
                uint32_t off = (uint32_t)(n * 128)
                             + (((uint32_t)(kbyt + kselB)) ^ ((n * 16) & 0x70));
                LDSM4(bh[nb], Bh + off);
                LDSM4(bl[nb], Bl + off);
            }
            #pragma unroll
            for (int mf = 0; mf < 4; ++mf)
                #pragma unroll
                for (int nf = 0; nf < 4; ++nf) {
                    const int nb = nf >> 1, ri = (nf & 1) * 2;
                    MMA_BF16(accS[mf][nf], ah[mf], bh[nb][ri], bh[nb][ri + 1]);
                    MMA_BF16(accS[mf][nf], ah[mf], bl[nb][ri], bl[nb][ri + 1]);
                    MMA_BF16(accS[mf][nf], al[mf], bh[nb][ri], bh[nb][ri + 1]);
                }
        }
    };

    int cur = 0;
    for (int kb = 0; kb < I; kb += 64) {
        // ---- big-chunk fill: base A (x) + base B (bw), hi/lo split ----
        #pragma unroll
        for (int rr = 0; rr < 8; ++rr) {
            int v = rr * THREADS + tid;
            int m = v >> 4, c4 = v & 15;
            float4 xv = *reinterpret_cast<const float4*>(
                &x[(size_t)(m0 + m) * I + kb + c4 * 4]);
            uint32_t h0w, l0w, h1w, l1w;
            bfsplit2(xv.x, xv.y, h0w, l0w);
            bfsplit2(xv.z, xv.w, h1w, l1w);
            uint32_t off = SW128((uint32_t)(m * 128 + c4 * 8));
            *reinterpret_cast<uint2*>(smb + A_BA_HI + off) = make_uint2(h0w, h1w);
            *reinterpret_cast<uint2*>(smb + A_BA_LO + off) = make_uint2(l0w, l1w);
        }
        #pragma unroll
        for (int rr = 0; rr < 16; ++rr) {
            int v = rr * THREADS + tid;
            int kp = v >> 7, n = v & 127;
            float b0 = bw[(size_t)(kb + 2 * kp) * O + n0 + n];
            float b1 = bw[(size_t)(kb + 2 * kp + 1) * O + n0 + n];
            uint32_t hw, lw;
            bfsplit2(b0, b1, hw, lw);
            uint32_t off = SW128((uint32_t)(n * 128 + kp * 4));
            *reinterpret_cast<uint32_t*>(smb + B_BA_HI + off) = hw;
            *reinterpret_cast<uint32_t*>(smb + B_BA_LO + off) = lw;
        }
        __syncthreads();

        // prologue: fill sub=0 into cur
        fill_spline(cur, kb, 0);
        __syncthreads();

        for (int sub = 0; sub < 8; ++sub) {
            if (sub < 7) fill_spline(cur ^ 1, kb, sub + 1);  // overlap with MMA below
            mma_spline(cur);
            if (sub == 0) {
                // base MMA (once per big-chunk)
                #pragma unroll
                for (int k16 = 0; k16 < 4; ++k16) {
                    const int kbyt = k16 * 32;
                    uint32_t ah[4][4], al[4][4];
                    #pragma unroll
                    for (int mf = 0; mf < 4; ++mf) {
                        int m = wm * 64 + mf * 16 + rowA_l;
                        uint32_t off = (uint32_t)(m * 128)
                                     + (((uint32_t)(kbyt + kselA)) ^ ((m * 16) & 0x70));
                        LDSM4(ah[mf], sbase + A_BA_HI + off);
                        LDSM4(al[mf], sbase + A_BA_LO + off);
                    }
                    uint32_t bh[2][4], bl[2][4];
                    #pragma unroll
                    for (int nb = 0; nb < 2; ++nb) {
                        int n = wn * 32 + nb * 16 + rowB_l;
                        uint32_t off = (uint32_t)(n * 128)
                                     + (((uint32_t)(kbyt + kselB)) ^ ((n * 16) & 0x70));
                        LDSM4(bh[nb], sbase + B_BA_HI + off);
                        LDSM4(bl[nb], sbase + B_BA_LO + off);
                    }
                    #pragma unroll
                    for (int mf = 0; mf < 4; ++mf)
                        #pragma unroll
                        for (int nf = 0; nf < 4; ++nf) {
                            const int nb = nf >> 1, ri = (nf & 1) * 2;
                            MMA_BF16(accB[mf][nf], ah[mf], bh[nb][ri], bh[nb][ri + 1]);
                            MMA_BF16(accB[mf][nf], ah[mf], bl[nb][ri], bl[nb][ri + 1]);
                            MMA_BF16(accB[mf][nf], al[mf], bh[nb][ri], bh[nb][ri + 1]);
                        }
                }
            }
            __syncthreads();
            cur ^= 1;
        }
    }

    // ---------------- epilogue ----------------
    const float snv = *snp;
    const int rq = lid >> 2, cq = (lid & 3) * 2;
    #pragma unroll
    for (int mf = 0; mf < 4; ++mf) {
        #pragma unroll
        for (int nf = 0; nf < 4; ++nf) {
            #pragma unroll
            for (int half = 0; half < 2; ++half) {
                int b = m0 + wm * 64 + mf * 16 + rq + half * 8;
                int obase = n0 + wn * 32 + nf * 8 + cq;
                float2 res;
                #pragma unroll
                for (int e = 0; e < 2; ++e) {
                    int o = obase + e;
                    float sv = accS[mf][nf][half * 2 + e];
                    float bv = accB[mf][nf][half * 2 + e];
                    float sg = 1.0f / (1.0f + __expf(-bv));
                    uint32_t li = (uint32_t)b * (uint32_t)O + (uint32_t)o;
                    uint32_t r0, r1;
                    threefry2x32_dev(nk0, nk1, 0u, li, r0, r1);
                    uint32_t bits = r0 ^ r1;
                    float f = __uint_as_float((bits >> 9) | 0x3f800000u) - 1.0f;
                    float uu = fmaxf(-0.99999994f, fmaf(f, 2.0f, -0.99999994f));
                    float nz = 1.41421356f * erfinvf(uu);
                    float val = bv * sg * sbp[o] + sv * ssp[o] + nz * snv;
                    if (e == 0) res.x = val; else res.y = val;
                }
                *reinterpret_cast<float2*>(&out[(size_t)b * O + obase]) = res;
            }
        }
    }
}

// ---------------- launch ----------------
extern "C" void kernel_launch(void* const* d_in, const int* in_sizes, int n_in,
                              void* d_out, int out_size) {
    const float* x = (const float*)d_in[0];
    const float* sw[4]; const float* bw[4]; const float* sb[4];
    const float* ss[4]; const float* sn[4];
    for (int li = 0; li < 4; ++li) {
        sw[li] = (const float*)d_in[1 + 5 * li + 0];
        bw[li] = (const float*)d_in[1 + 5 * li + 1];
        sb[li] = (const float*)d_in[1 + 5 * li + 2];
        ss[li] = (const float*)d_in[1 + 5 * li + 3];
        sn[li] = (const float*)d_in[1 + 5 * li + 4];
    }
    const int B = in_sizes[0] / 1024;   // 8192
    float* out  = (float*)d_out;
    float* xrec = out;                       // [B, 1024]
    float* z    = out + (size_t)B * 1024;    // [B, 256]

    float* h0; cudaGetSymbolAddress((void**)&h0, g_h0);
    float* h2; cudaGetSymbolAddress((void**)&h2, g_h2);

    uint32_t fk0[4], fk1[4];
    for (int li = 0; li < 4; ++li)
        threefry2x32_host(0u, 42u, 0u, (uint32_t)li, fk0[li], fk1[li]);

    cudaFuncSetAttribute(kan_mma_kernel,
                         cudaFuncAttributeMaxDynamicSharedMemorySize, SMEM_DYN);

    dim3 blk(THREADS);
    {   // L0: 1024 -> 2048
        dim3 g(B / 128, 2048 / 128);
        kan_mma_kernel<<<g, blk, SMEM_DYN>>>(x, sw[0], bw[0], sb[0], ss[0], sn[0],
                                             h0, 1024, 2048, fk0[0], fk1[0]);
    }
    {   // L1: 2048 -> 256 (z output)
        dim3 g(B / 128, 256 / 128);
        kan_mma_kernel<<<g, blk, SMEM_DYN>>>(h0, sw[1], bw[1], sb[1], ss[1], sn[1],
                                             z, 2048, 256, fk0[1], fk1[1]);
    }
    {   // L2: 256 -> 2048
        dim3 g(B / 128, 2048 / 128);
        kan_mma_kernel<<<g, blk, SMEM_DYN>>>(z, sw[2], bw[2], sb[2], ss[2], sn[2],
                                             h2, 256, 2048, fk0[2], fk1[2]);
    }
    {   // L3: 2048 -> 1024 (x_rec output)
        dim3 g(B / 128, 1024 / 128);
        kan_mma_kernel<<<g, blk, SMEM_DYN>>>(h2, sw[3], bw[3], sb[3], ss[3], sn[3],
                                             xrec, 2048, 1024, fk0[3], fk1[3]);
    }
}

// round 5
// speedup vs baseline: 3.2325x; 1.3314x over previous
#include <cuda_runtime.h>
#include <cuda_bf16.h>
#include <cstdint>
#include <cstddef>

#define THREADS 512

// Scratch activations (allocation-free)
__device__ float g_h0[8192u * 2048u];
__device__ float g_h2[8192u * 2048u];

// Packed pre-swizzled bf16 hi/lo weights.
// sw blocks: per (layer, ntile, kchunk64, sub): 32KB = [hi 16KB | lo 16KB],
//   hi block = [128 n][64 kk] bf16, 128B rows, SW128 swizzled.
// bw blocks: per (layer, ntile, kchunk64): 32KB same layout ([128 n][64 k]).
__device__ char g_swp[167772160];   // 160MB
__device__ char g_bwp[20971520];    // 20MB

// Gaussian basis recurrence: e_g = e0 * u^g * exp(-2e-4*g^2)
__constant__ float RAT[7] = {0.99980002f, 0.99940018f, 0.99900050f,
                             0.99860098f, 0.99820162f, 0.99780242f, 0.99740338f};

// ---------------- threefry2x32 (JAX-compatible, validated) ----------------
__device__ __forceinline__ uint32_t rotl32d(uint32_t v, int d) {
    return __funnelshift_l(v, v, d);
}
__device__ __forceinline__ void threefry2x32_dev(uint32_t k0, uint32_t k1,
                                                 uint32_t c0, uint32_t c1,
                                                 uint32_t& o0, uint32_t& o1) {
    uint32_t ks2 = k0 ^ k1 ^ 0x1BD11BDAu;
    uint32_t x0 = c0 + k0, x1 = c1 + k1;
#define TF_RND(r) { x0 += x1; x1 = rotl32d(x1, r); x1 ^= x0; }
    TF_RND(13) TF_RND(15) TF_RND(26) TF_RND(6)
    x0 += k1;  x1 += ks2 + 1u;
    TF_RND(17) TF_RND(29) TF_RND(16) TF_RND(24)
    x0 += ks2; x1 += k0 + 2u;
    TF_RND(13) TF_RND(15) TF_RND(26) TF_RND(6)
    x0 += k0;  x1 += k1 + 3u;
    TF_RND(17) TF_RND(29) TF_RND(16) TF_RND(24)
    x0 += k1;  x1 += ks2 + 4u;
    TF_RND(13) TF_RND(15) TF_RND(26) TF_RND(6)
    x0 += ks2; x1 += k0 + 5u;
#undef TF_RND
    o0 = x0; o1 = x1;
}
static inline uint32_t rotl32h(uint32_t v, int d) {
    return (v << d) | (v >> (32 - d));
}
static void threefry2x32_host(uint32_t k0, uint32_t k1, uint32_t c0, uint32_t c1,
                              uint32_t& o0, uint32_t& o1) {
    uint32_t ks2 = k0 ^ k1 ^ 0x1BD11BDAu;
    uint32_t x0 = c0 + k0, x1 = c1 + k1;
#define TF_RND(r) { x0 += x1; x1 = rotl32h(x1, r); x1 ^= x0; }
    TF_RND(13) TF_RND(15) TF_RND(26) TF_RND(6)
    x0 += k1;  x1 += ks2 + 1u;
    TF_RND(17) TF_RND(29) TF_RND(16) TF_RND(24)
    x0 += ks2; x1 += k0 + 2u;
    TF_RND(13) TF_RND(15) TF_RND(26) TF_RND(6)
    x0 += k0;  x1 += k1 + 3u;
    TF_RND(17) TF_RND(29) TF_RND(16) TF_RND(24)
    x0 += k1;  x1 += ks2 + 4u;
    TF_RND(13) TF_RND(15) TF_RND(26) TF_RND(6)
    x0 += ks2; x1 += k0 + 5u;
#undef TF_RND
    o0 = x0; o1 = x1;
}

// ---------------- helpers ----------------
__device__ __forceinline__ uint32_t smem_u32(const void* p) {
    uint32_t a;
    asm("{ .reg .u64 t; cvta.to.shared.u64 t, %1; cvt.u32.u64 %0, t; }"
        : "=r"(a) : "l"(p));
    return a;
}
#define SW128(o) ((o) ^ ((((uint32_t)(o)) >> 3) & 0x70))

#define LDSM4(rv, a) \
    asm volatile("ldmatrix.sync.aligned.m8n8.x4.shared.b16 {%0,%1,%2,%3}, [%4];" \
        : "=r"((rv)[0]), "=r"((rv)[1]), "=r"((rv)[2]), "=r"((rv)[3]) \
        : "r"(a))

#define MMA_BF16(c, a, b0, b1) \
    asm volatile("mma.sync.aligned.m16n8k16.row.col.f32.bf16.bf16.f32 " \
        "{%0,%1,%2,%3}, {%4,%5,%6,%7}, {%8,%9}, {%0,%1,%2,%3};" \
        : "+f"((c)[0]), "+f"((c)[1]), "+f"((c)[2]), "+f"((c)[3]) \
        : "r"((a)[0]), "r"((a)[1]), "r"((a)[2]), "r"((a)[3]), "r"(b0), "r"(b1))

#define CP_ASYNC16(dst, src) \
    asm volatile("cp.async.cg.shared.global [%0], [%1], 16;" \
                 :: "r"((uint32_t)(dst)), "l"(src) : "memory")
#define CP_COMMIT() asm volatile("cp.async.commit_group;" ::: "memory")
#define CP_WAIT0()  asm volatile("cp.async.wait_group 0;" ::: "memory")

__device__ __forceinline__ void bfsplit2(float a, float b, uint32_t& hi2, uint32_t& lo2) {
    asm("cvt.rn.bf16x2.f32 %0, %1, %2;" : "=r"(hi2) : "f"(b), "f"(a));
    __nv_bfloat162 hv = *reinterpret_cast<__nv_bfloat162*>(&hi2);
    float ra = a - __bfloat162float(hv.x);
    float rb = b - __bfloat162float(hv.y);
    asm("cvt.rn.bf16x2.f32 %0, %1, %2;" : "=r"(lo2) : "f"(rb), "f"(ra));
}

// ---------------- pack kernels ----------------
__global__ void pack_sw_kernel(const float* __restrict__ sw, char* __restrict__ dst,
                               int I, int O) {
    size_t idx = (size_t)blockIdx.x * blockDim.x + threadIdx.x;
    size_t total = (size_t)I * O * 4;
    if (idx >= total) return;
    int g2 = (int)(idx & 3) * 2;
    size_t rem = idx >> 2;
    int o = (int)(rem % O);
    int i = (int)(rem / O);
    float2 wv = *reinterpret_cast<const float2*>(&sw[((size_t)i * O + o) * 8 + g2]);
    uint32_t hw, lw;
    bfsplit2(wv.x, wv.y, hw, lw);
    int t = o >> 7, n = o & 127, c = i >> 6, s = (i >> 3) & 7, ii = i & 7;
    size_t blk = (((size_t)t * (I >> 6) + c) * 8 + s) * 32768;
    uint32_t off = SW128((uint32_t)(n * 128 + (ii * 8 + g2) * 2));
    *reinterpret_cast<uint32_t*>(dst + blk + off) = hw;
    *reinterpret_cast<uint32_t*>(dst + blk + 16384 + off) = lw;
}

__global__ void pack_bw_kernel(const float* __restrict__ bw, char* __restrict__ dst,
                               int I, int O) {
    size_t idx = (size_t)blockIdx.x * blockDim.x + threadIdx.x;
    size_t total = (size_t)O * (I >> 1);
    if (idx >= total) return;
    int o = (int)(idx % O);
    int kp = (int)(idx / O);
    float b0 = bw[(size_t)(2 * kp) * O + o];
    float b1 = bw[(size_t)(2 * kp + 1) * O + o];
    uint32_t hw, lw;
    bfsplit2(b0, b1, hw, lw);
    int t = o >> 7, n = o & 127;
    int c = (2 * kp) >> 6, klocal = (2 * kp) & 63;
    size_t blk = ((size_t)t * (I >> 6) + c) * 32768;
    uint32_t off = SW128((uint32_t)(n * 128 + klocal * 2));
    *reinterpret_cast<uint32_t*>(dst + blk + off) = hw;
    *reinterpret_cast<uint32_t*>(dst + blk + 16384 + off) = lw;
}

// ---------------- SMEM layout ----------------
static constexpr int SP_BUF_STRIDE = 65536;
static constexpr int SP_A_HI = 0;
static constexpr int SP_A_LO = 16384;
static constexpr int SP_B    = 32768;      // 32KB block [hi|lo] straight copy
static constexpr int A_BA_HI = 131072;
static constexpr int A_BA_LO = 147456;
static constexpr int B_BA    = 163840;     // 32KB block [hi|lo]
static constexpr int SMEM_SZ = 196608;
static constexpr int SMEM_DYN = SMEM_SZ + 1024;

// ---------------- fused KAN layer: 16 warps, packed weights ----------------
__global__ __launch_bounds__(THREADS, 1)
void kan_mma_kernel(const float* __restrict__ x,
                    const char* __restrict__ swp,   // packed layer base
                    const char* __restrict__ bwp,   // packed layer base
                    const float* __restrict__ sbp,
                    const float* __restrict__ ssp,
                    const float* __restrict__ snp,
                    float* __restrict__ out,
                    int I, int O,
                    uint32_t nk0, uint32_t nk1) {
    extern __shared__ char raw[];
    const uint32_t rawu = smem_u32(raw);
    const uint32_t sbase = (rawu + 1023u) & ~1023u;
    char* smb = raw + (sbase - rawu);

    const int tid = threadIdx.x;
    const int wid = tid >> 5;
    const int lid = tid & 31;
    const int wm  = wid >> 2;       // 0..3, 32 m rows each
    const int wn  = wid & 3;        // 0..3, 32 n cols each
    const int m0  = blockIdx.x * 128;   // m fastest (L2 reuse of sw)
    const int n0  = blockIdx.y * 128;

    const int q = lid >> 3, r = lid & 7;
    const int rowA_l = r + (q & 1) * 8;
    const int kselA  = (q >> 1) * 16;
    const int rowB_l = r + (q >> 1) * 8;
    const int kselB  = (q & 1) * 16;

    float accS[2][4][4];
    float accB[2][4][4];
    #pragma unroll
    for (int a = 0; a < 2; ++a)
        #pragma unroll
        for (int b = 0; b < 4; ++b)
            #pragma unroll
            for (int e = 0; e < 4; ++e) { accS[a][b][e] = 0.f; accB[a][b][e] = 0.f; }

    const int nkc = I >> 6;                 // k-chunks of 64
    const size_t sw_tile = (size_t)(n0 >> 7) * nkc;

    // ---- basis fill into spline buffer (reads x from base-A hi/lo tiles) ----
    auto basis_fill = [&](int buf, int sub) {
        char* bA_hi = smb + buf * SP_BUF_STRIDE + SP_A_HI;
        char* bA_lo = smb + buf * SP_BUF_STRIDE + SP_A_LO;
        #pragma unroll
        for (int rr = 0; rr < 2; ++rr) {
            int t = rr * THREADS + tid;      // 1024 (m, il) tasks
            int m = t >> 3, il = t & 7;
            uint32_t xoff = SW128((uint32_t)(m * 128 + (sub * 8 + il) * 2));
            float xh = __bfloat162float(
                *reinterpret_cast<const __nv_bfloat16*>(smb + A_BA_HI + xoff));
            float xl = __bfloat162float(
                *reinterpret_cast<const __nv_bfloat16*>(smb + A_BA_LO + xoff));
            float xv = xh + xl;
            float d = xv + 0.044f;
            float e = __expf(-3.125f * d * d);
            float u = __expf(0.05f * d);
            float v[8];
            v[0] = e;
            #pragma unroll
            for (int g = 1; g < 8; ++g) v[g] = v[g - 1] * u * RAT[g - 1];
            uint32_t hw[4], lw[4];
            #pragma unroll
            for (int qq = 0; qq < 4; ++qq)
                bfsplit2(v[2 * qq], v[2 * qq + 1], hw[qq], lw[qq]);
            uint32_t off = SW128((uint32_t)(m * 128 + il * 16));
            *reinterpret_cast<uint4*>(bA_hi + off) = make_uint4(hw[0], hw[1], hw[2], hw[3]);
            *reinterpret_cast<uint4*>(bA_lo + off) = make_uint4(lw[0], lw[1], lw[2], lw[3]);
        }
    };

    // ---- spline B copy: 32KB pre-swizzled block via cp.async ----
    auto spline_b_copy = [&](int buf, int kb, int sub) {
        const char* blk = swp + ((sw_tile + (kb >> 6)) * 8 + sub) * 32768;
        uint32_t dst = sbase + buf * SP_BUF_STRIDE + SP_B;
        #pragma unroll
        for (int rr = 0; rr < 4; ++rr) {
            uint32_t off = (uint32_t)(rr * THREADS + tid) * 16;
            CP_ASYNC16(dst + off, blk + off);
        }
    };

    // ---- MMA over one spline buffer ----
    auto mma_spline = [&](int buf) {
        const uint32_t Ah = sbase + buf * SP_BUF_STRIDE + SP_A_HI;
        const uint32_t Al = sbase + buf * SP_BUF_STRIDE + SP_A_LO;
        const uint32_t Bh = sbase + buf * SP_BUF_STRIDE + SP_B;
        const uint32_t Bl = Bh + 16384;
        #pragma unroll
        for (int k16 = 0; k16 < 4; ++k16) {
            const int kbyt = k16 * 32;
            uint32_t ah[2][4], al[2][4];
            #pragma unroll
            for (int mf = 0; mf < 2; ++mf) {
                int m = wm * 32 + mf * 16 + rowA_l;
                uint32_t off = (uint32_t)(m * 128)
                             + (((uint32_t)(kbyt + kselA)) ^ ((m * 16) & 0x70));
                LDSM4(ah[mf], Ah + off);
                LDSM4(al[mf], Al + off);
            }
            uint32_t bh[2][4], bl[2][4];
            #pragma unroll
            for (int nb = 0; nb < 2; ++nb) {
                int n = wn * 32 + nb * 16 + rowB_l;
                uint32_t off = (uint32_t)(n * 128)
                             + (((uint32_t)(kbyt + kselB)) ^ ((n * 16) & 0x70));
                LDSM4(bh[nb], Bh + off);
                LDSM4(bl[nb], Bl + off);
            }
            #pragma unroll
            for (int mf = 0; mf < 2; ++mf)
                #pragma unroll
                for (int nf = 0; nf < 4; ++nf) {
                    const int nb = nf >> 1, ri = (nf & 1) * 2;
                    MMA_BF16(accS[mf][nf], ah[mf], bh[nb][ri], bh[nb][ri + 1]);
                    MMA_BF16(accS[mf][nf], ah[mf], bl[nb][ri], bl[nb][ri + 1]);
                    MMA_BF16(accS[mf][nf], al[mf], bh[nb][ri], bh[nb][ri + 1]);
                }
        }
    };

    auto mma_base = [&]() {
        const uint32_t Ah = sbase + A_BA_HI, Al = sbase + A_BA_LO;
        const uint32_t Bh = sbase + B_BA, Bl = Bh + 16384;
        #pragma unroll
        for (int k16 = 0; k16 < 4; ++k16) {
            const int kbyt = k16 * 32;
            uint32_t ah[2][4], al[2][4];
            #pragma unroll
            for (int mf = 0; mf < 2; ++mf) {
                int m = wm * 32 + mf * 16 + rowA_l;
                uint32_t off = (uint32_t)(m * 128)
                             + (((uint32_t)(kbyt + kselA)) ^ ((m * 16) & 0x70));
                LDSM4(ah[mf], Ah + off);
                LDSM4(al[mf], Al + off);
            }
            uint32_t bh[2][4], bl[2][4];
            #pragma unroll
            for (int nb = 0; nb < 2; ++nb) {
                int n = wn * 32 + nb * 16 + rowB_l;
                uint32_t off = (uint32_t)(n * 128)
                             + (((uint32_t)(kbyt + kselB)) ^ ((n * 16) & 0x70));
                LDSM4(bh[nb], Bh + off);
                LDSM4(bl[nb], Bl + off);
            }
            #pragma unroll
            for (int mf = 0; mf < 2; ++mf)
                #pragma unroll
                for (int nf = 0; nf < 4; ++nf) {
                    const int nb = nf >> 1, ri = (nf & 1) * 2;
                    MMA_BF16(accB[mf][nf], ah[mf], bh[nb][ri], bh[nb][ri + 1]);
                    MMA_BF16(accB[mf][nf], ah[mf], bl[nb][ri], bl[nb][ri + 1]);
                    MMA_BF16(accB[mf][nf], al[mf], bh[nb][ri], bh[nb][ri + 1]);
                }
        }
    };

    int cur = 0;
    for (int kb = 0; kb < I; kb += 64) {
        // base A (x) fill: 2048 float4 tasks
        #pragma unroll
        for (int rr = 0; rr < 4; ++rr) {
            int v = rr * THREADS + tid;
            int m = v >> 4, c4 = v & 15;
            float4 xv = *reinterpret_cast<const float4*>(
                &x[(size_t)(m0 + m) * I + kb + c4 * 4]);
            uint32_t h0w, l0w, h1w, l1w;
            bfsplit2(xv.x, xv.y, h0w, l0w);
            bfsplit2(xv.z, xv.w, h1w, l1w);
            uint32_t off = SW128((uint32_t)(m * 128 + c4 * 8));
            *reinterpret_cast<uint2*>(smb + A_BA_HI + off) = make_uint2(h0w, h1w);
            *reinterpret_cast<uint2*>(smb + A_BA_LO + off) = make_uint2(l0w, l1w);
        }
        // base B: 32KB pre-swizzled block
        {
            const char* blk = bwp + (sw_tile + (kb >> 6)) * 32768;
            #pragma unroll
            for (int rr = 0; rr < 4; ++rr) {
                uint32_t off = (uint32_t)(rr * THREADS + tid) * 16;
                CP_ASYNC16(sbase + B_BA + off, blk + off);
            }
            CP_COMMIT();
        }
        __syncthreads();    // base A visible for basis fill

        basis_fill(cur, 0);
        spline_b_copy(cur, kb, 0);
        CP_COMMIT();
        CP_WAIT0();
        __syncthreads();

        for (int sub = 0; sub < 8; ++sub) {
            if (sub < 7) {
                basis_fill(cur ^ 1, sub + 1);
                spline_b_copy(cur ^ 1, kb, sub + 1);
                CP_COMMIT();
            }
            mma_spline(cur);
            if (sub == 0) mma_base();
            CP_WAIT0();
            __syncthreads();
            cur ^= 1;
        }
    }

    // ---------------- epilogue ----------------
    const float snv = *snp;
    const int rq = lid >> 2, cq = (lid & 3) * 2;
    #pragma unroll
    for (int mf = 0; mf < 2; ++mf) {
        #pragma unroll
        for (int nf = 0; nf < 4; ++nf) {
            #pragma unroll
            for (int half = 0; half < 2; ++half) {
                int b = m0 + wm * 32 + mf * 16 + rq + half * 8;
                int obase = n0 + wn * 32 + nf * 8 + cq;
                float2 res;
                #pragma unroll
                for (int e = 0; e < 2; ++e) {
                    int o = obase + e;
                    float sv = accS[mf][nf][half * 2 + e];
                    float bv = accB[mf][nf][half * 2 + e];
                    float sg = 1.0f / (1.0f + __expf(-bv));
                    uint32_t li = (uint32_t)b * (uint32_t)O + (uint32_t)o;
                    uint32_t r0, r1;
                    threefry2x32_dev(nk0, nk1, 0u, li, r0, r1);
                    uint32_t bits = r0 ^ r1;
                    float f = __uint_as_float((bits >> 9) | 0x3f800000u) - 1.0f;
                    float uu = fmaxf(-0.99999994f, fmaf(f, 2.0f, -0.99999994f));
                    float nz = 1.41421356f * erfinvf(uu);
                    float val = bv * sg * sbp[o] + sv * ssp[o] + nz * snv;
                    if (e == 0) res.x = val; else res.y = val;
                }
                *reinterpret_cast<float2*>(&out[(size_t)b * O + obase]) = res;
            }
        }
    }
}

// ---------------- launch ----------------
extern "C" void kernel_launch(void* const* d_in, const int* in_sizes, int n_in,
                              void* d_out, int out_size) {
    const float* x = (const float*)d_in[0];
    const float* sw[4]; const float* bw[4]; const float* sb[4];
    const float* ss[4]; const float* sn[4];
    for (int li = 0; li < 4; ++li) {
        sw[li] = (const float*)d_in[1 + 5 * li + 0];
        bw[li] = (const float*)d_in[1 + 5 * li + 1];
        sb[li] = (const float*)d_in[1 + 5 * li + 2];
        ss[li] = (const float*)d_in[1 + 5 * li + 3];
        sn[li] = (const float*)d_in[1 + 5 * li + 4];
    }
    const int B = in_sizes[0] / 1024;   // 8192
    float* out  = (float*)d_out;
    float* xrec = out;
    float* z    = out + (size_t)B * 1024;

    float* h0; cudaGetSymbolAddress((void**)&h0, g_h0);
    float* h2; cudaGetSymbolAddress((void**)&h2, g_h2);
    char* swp; cudaGetSymbolAddress((void**)&swp, g_swp);
    char* bwp; cudaGetSymbolAddress((void**)&bwp, g_bwp);

    const int Is[4] = {1024, 2048, 256, 2048};
    const int Os[4] = {2048, 256, 2048, 1024};
    // packed byte offsets: ntiles*(I/64)*8*32768 (sw), ntiles*(I/64)*32768 (bw)
    size_t sw_off[4], bw_off[4];
    size_t so = 0, bo = 0;
    for (int li = 0; li < 4; ++li) {
        sw_off[li] = so; bw_off[li] = bo;
        so += (size_t)(Os[li] / 128) * (Is[li] / 64) * 8 * 32768;
        bo += (size_t)(Os[li] / 128) * (Is[li] / 64) * 32768;
    }

    uint32_t fk0[4], fk1[4];
    for (int li = 0; li < 4; ++li)
        threefry2x32_host(0u, 42u, 0u, (uint32_t)li, fk0[li], fk1[li]);

    cudaFuncSetAttribute(kan_mma_kernel,
                         cudaFuncAttributeMaxDynamicSharedMemorySize, SMEM_DYN);

    // ---- pack weights ----
    for (int li = 0; li < 4; ++li) {
        size_t tot = (size_t)Is[li] * Os[li] * 4;
        pack_sw_kernel<<<(unsigned)((tot + 255) / 256), 256>>>(
            sw[li], swp + sw_off[li], Is[li], Os[li]);
        size_t totb = (size_t)Os[li] * (Is[li] / 2);
        pack_bw_kernel<<<(unsigned)((totb + 255) / 256), 256>>>(
            bw[li], bwp + bw_off[li], Is[li], Os[li]);
    }

    dim3 blk(THREADS);
    const float* ins[4]  = {x, h0, z, h2};
    float* outs[4]       = {h0, z, h2, xrec};
    for (int li = 0; li < 4; ++li) {
        dim3 g(B / 128, Os[li] / 128);
        kan_mma_kernel<<<g, blk, SMEM_DYN>>>(
            ins[li], swp + sw_off[li], bwp + bw_off[li],
            sb[li], ss[li], sn[li], outs[li],
            Is[li], Os[li], fk0[li], fk1[li]);
    }
}

// round 6
// speedup vs baseline: 3.6394x; 1.1259x over previous
#include <cuda_runtime.h>
#include <cuda_bf16.h>
#include <cstdint>
#include <cstddef>

#define THREADS 512

// Scratch activations (allocation-free)
__device__ float g_h0[8192u * 2048u];
__device__ float g_h2[8192u * 2048u];

// Packed pre-swizzled bf16 hi/lo weights (same layout as R5):
// sw blocks: per (layer, ntile, kchunk64, sub): 32KB = [hi 16KB | lo 16KB]
// bw blocks: per (layer, ntile, kchunk64): 32KB
__device__ __align__(128) char g_swp[167772160];   // 160MB
__device__ __align__(128) char g_bwp[20971520];    // 20MB
// Packed pre-swizzled bf16 hi/lo A-blocks, reused per layer:
// per (mtile, kchunk64, sub 0..8): 32KB. sub 0..7 = basis tiles, sub 8 = x tile.
// max: 64 mtiles * 32 kchunks * 9 * 32768 = 603,979,776 B
__device__ __align__(128) char g_ab[603979776];

// Gaussian basis recurrence: e_g = e0 * u^g * exp(-2e-4*g^2)
__constant__ float RAT[7] = {0.99980002f, 0.99940018f, 0.99900050f,
                             0.99860098f, 0.99820162f, 0.99780242f, 0.99740338f};

// ---------------- threefry2x32 (JAX-compatible, validated) ----------------
__device__ __forceinline__ uint32_t rotl32d(uint32_t v, int d) {
    return __funnelshift_l(v, v, d);
}
__device__ __forceinline__ void threefry2x32_dev(uint32_t k0, uint32_t k1,
                                                 uint32_t c0, uint32_t c1,
                                                 uint32_t& o0, uint32_t& o1) {
    uint32_t ks2 = k0 ^ k1 ^ 0x1BD11BDAu;
    uint32_t x0 = c0 + k0, x1 = c1 + k1;
#define TF_RND(r) { x0 += x1; x1 = rotl32d(x1, r); x1 ^= x0; }
    TF_RND(13) TF_RND(15) TF_RND(26) TF_RND(6)
    x0 += k1;  x1 += ks2 + 1u;
    TF_RND(17) TF_RND(29) TF_RND(16) TF_RND(24)
    x0 += ks2; x1 += k0 + 2u;
    TF_RND(13) TF_RND(15) TF_RND(26) TF_RND(6)
    x0 += k0;  x1 += k1 + 3u;
    TF_RND(17) TF_RND(29) TF_RND(16) TF_RND(24)
    x0 += k1;  x1 += ks2 + 4u;
    TF_RND(13) TF_RND(15) TF_RND(26) TF_RND(6)
    x0 += ks2; x1 += k0 + 5u;
#undef TF_RND
    o0 = x0; o1 = x1;
}
static inline uint32_t rotl32h(uint32_t v, int d) {
    return (v << d) | (v >> (32 - d));
}
static void threefry2x32_host(uint32_t k0, uint32_t k1, uint32_t c0, uint32_t c1,
                              uint32_t& o0, uint32_t& o1) {
    uint32_t ks2 = k0 ^ k1 ^ 0x1BD11BDAu;
    uint32_t x0 = c0 + k0, x1 = c1 + k1;
#define TF_RND(r) { x0 += x1; x1 = rotl32h(x1, r); x1 ^= x0; }
    TF_RND(13) TF_RND(15) TF_RND(26) TF_RND(6)
    x0 += k1;  x1 += ks2 + 1u;
    TF_RND(17) TF_RND(29) TF_RND(16) TF_RND(24)
    x0 += ks2; x1 += k0 + 2u;
    TF_RND(13) TF_RND(15) TF_RND(26) TF_RND(6)
    x0 += k0;  x1 += k1 + 3u;
    TF_RND(17) TF_RND(29) TF_RND(16) TF_RND(24)
    x0 += k1;  x1 += ks2 + 4u;
    TF_RND(13) TF_RND(15) TF_RND(26) TF_RND(6)
    x0 += ks2; x1 += k0 + 5u;
#undef TF_RND
    o0 = x0; o1 = x1;
}

// ---------------- helpers ----------------
__device__ __forceinline__ uint32_t smem_u32(const void* p) {
    uint32_t a;
    asm("{ .reg .u64 t; cvta.to.shared.u64 t, %1; cvt.u32.u64 %0, t; }"
        : "=r"(a) : "l"(p));
    return a;
}
#define SW128(o) ((o) ^ ((((uint32_t)(o)) >> 3) & 0x70))

#define LDSM4(rv, a) \
    asm volatile("ldmatrix.sync.aligned.m8n8.x4.shared.b16 {%0,%1,%2,%3}, [%4];" \
        : "=r"((rv)[0]), "=r"((rv)[1]), "=r"((rv)[2]), "=r"((rv)[3]) \
        : "r"(a))

#define MMA_BF16(c, a, b0, b1) \
    asm volatile("mma.sync.aligned.m16n8k16.row.col.f32.bf16.bf16.f32 " \
        "{%0,%1,%2,%3}, {%4,%5,%6,%7}, {%8,%9}, {%0,%1,%2,%3};" \
        : "+f"((c)[0]), "+f"((c)[1]), "+f"((c)[2]), "+f"((c)[3]) \
        : "r"((a)[0]), "r"((a)[1]), "r"((a)[2]), "r"((a)[3]), "r"(b0), "r"(b1))

#define CP_ASYNC16(dst, src) \
    asm volatile("cp.async.cg.shared.global [%0], [%1], 16;" \
                 :: "r"((uint32_t)(dst)), "l"(src) : "memory")
#define CP_COMMIT() asm volatile("cp.async.commit_group;" ::: "memory")
#define CP_WAIT0()  asm volatile("cp.async.wait_group 0;" ::: "memory")
#define CP_WAIT1()  asm volatile("cp.async.wait_group 1;" ::: "memory")

__device__ __forceinline__ void bfsplit2(float a, float b, uint32_t& hi2, uint32_t& lo2) {
    asm("cvt.rn.bf16x2.f32 %0, %1, %2;" : "=r"(hi2) : "f"(b), "f"(a));
    __nv_bfloat162 hv = *reinterpret_cast<__nv_bfloat162*>(&hi2);
    float ra = a - __bfloat162float(hv.x);
    float rb = b - __bfloat162float(hv.y);
    asm("cvt.rn.bf16x2.f32 %0, %1, %2;" : "=r"(lo2) : "f"(rb), "f"(ra));
}

// ---------------- pack kernels ----------------
__global__ void pack_sw_kernel(const float* __restrict__ sw, char* __restrict__ dst,
                               int I, int O) {
    size_t idx = (size_t)blockIdx.x * blockDim.x + threadIdx.x;
    size_t total = (size_t)I * O * 4;
    if (idx >= total) return;
    int g2 = (int)(idx & 3) * 2;
    size_t rem = idx >> 2;
    int o = (int)(rem % O);
    int i = (int)(rem / O);
    float2 wv = *reinterpret_cast<const float2*>(&sw[((size_t)i * O + o) * 8 + g2]);
    uint32_t hw, lw;
    bfsplit2(wv.x, wv.y, hw, lw);
    int t = o >> 7, n = o & 127, c = i >> 6, s = (i >> 3) & 7, ii = i & 7;
    size_t blk = (((size_t)t * (I >> 6) + c) * 8 + s) * 32768;
    uint32_t off = SW128((uint32_t)(n * 128 + (ii * 8 + g2) * 2));
    *reinterpret_cast<uint32_t*>(dst + blk + off) = hw;
    *reinterpret_cast<uint32_t*>(dst + blk + 16384 + off) = lw;
}

__global__ void pack_bw_kernel(const float* __restrict__ bw, char* __restrict__ dst,
                               int I, int O) {
    size_t idx = (size_t)blockIdx.x * blockDim.x + threadIdx.x;
    size_t total = (size_t)O * (I >> 1);
    if (idx >= total) return;
    int o = (int)(idx % O);
    int kp = (int)(idx / O);
    float b0 = bw[(size_t)(2 * kp) * O + o];
    float b1 = bw[(size_t)(2 * kp + 1) * O + o];
    uint32_t hw, lw;
    bfsplit2(b0, b1, hw, lw);
    int t = o >> 7, n = o & 127;
    int c = (2 * kp) >> 6, klocal = (2 * kp) & 63;
    size_t blk = ((size_t)t * (I >> 6) + c) * 32768;
    uint32_t off = SW128((uint32_t)(n * 128 + klocal * 2));
    *reinterpret_cast<uint32_t*>(dst + blk + off) = hw;
    *reinterpret_cast<uint32_t*>(dst + blk + 16384 + off) = lw;
}

// basis tiles: one block per (mtile, kchunk, sub); 256 threads, 4 tasks each
__global__ void pack_bases_kernel(const float* __restrict__ act,
                                  char* __restrict__ ab, int I, int nkc) {
    int bid = blockIdx.x;
    int sub = bid & 7;
    int t = bid >> 3;
    int kc = t % nkc;
    int mt = t / nkc;
    char* blk = ab + (((size_t)mt * nkc + kc) * 9 + sub) * 32768;
    int tid = threadIdx.x;
    #pragma unroll
    for (int rr = 0; rr < 4; ++rr) {
        int v = rr * 256 + tid;          // 1024 (mloc, il) tasks
        int mloc = v >> 3, il = v & 7;
        float xv = act[(size_t)(mt * 128 + mloc) * I + kc * 64 + sub * 8 + il];
        float d = xv + 0.044f;
        float e = __expf(-3.125f * d * d);
        float u = __expf(0.05f * d);
        float vv[8];
        vv[0] = e;
        #pragma unroll
        for (int g = 1; g < 8; ++g) vv[g] = vv[g - 1] * u * RAT[g - 1];
        uint32_t hw[4], lw[4];
        #pragma unroll
        for (int qq = 0; qq < 4; ++qq)
            bfsplit2(vv[2 * qq], vv[2 * qq + 1], hw[qq], lw[qq]);
        uint32_t off = SW128((uint32_t)(mloc * 128 + il * 16));
        *reinterpret_cast<uint4*>(blk + off) = make_uint4(hw[0], hw[1], hw[2], hw[3]);
        *reinterpret_cast<uint4*>(blk + 16384 + off) = make_uint4(lw[0], lw[1], lw[2], lw[3]);
    }
}

// x tiles (sub 8): one block per (mtile, kchunk); 256 threads, 8 tasks each
__global__ void pack_x_kernel(const float* __restrict__ act,
                              char* __restrict__ ab, int I, int nkc) {
    int bid = blockIdx.x;
    int kc = bid % nkc;
    int mt = bid / nkc;
    char* blk = ab + (((size_t)mt * nkc + kc) * 9 + 8) * 32768;
    int tid = threadIdx.x;
    #pragma unroll
    for (int rr = 0; rr < 8; ++rr) {
        int v = rr * 256 + tid;          // 2048 (mloc, c4) tasks
        int mloc = v >> 4, c4 = v & 15;
        float4 xv = *reinterpret_cast<const float4*>(
            &act[(size_t)(mt * 128 + mloc) * I + kc * 64 + c4 * 4]);
        uint32_t h0w, l0w, h1w, l1w;
        bfsplit2(xv.x, xv.y, h0w, l0w);
        bfsplit2(xv.z, xv.w, h1w, l1w);
        uint32_t off = SW128((uint32_t)(mloc * 128 + c4 * 8));
        *reinterpret_cast<uint2*>(blk + off) = make_uint2(h0w, h1w);
        *reinterpret_cast<uint2*>(blk + 16384 + off) = make_uint2(l0w, l1w);
    }
}

// ---------------- SMEM: 3-stage ring, 64KB per stage ----------------
// stage: A_hi | A_lo | B_hi | B_lo at +0 / +16K / +32K / +48K
static constexpr int STAGE_STRIDE = 65536;
static constexpr int NSTAGE = 3;
static constexpr int SMEM_SZ = NSTAGE * STAGE_STRIDE;   // 192KB
static constexpr int SMEM_DYN = SMEM_SZ + 1024;

// ---------------- main kernel: pure packed-GEMM pipeline ----------------
__global__ __launch_bounds__(THREADS, 1)
void kan_mma_kernel(const char* __restrict__ ab,
                    const char* __restrict__ swp,
                    const char* __restrict__ bwp,
                    const float* __restrict__ sbp,
                    const float* __restrict__ ssp,
                    const float* __restrict__ snp,
                    float* __restrict__ out,
                    int nkc, int O,
                    uint32_t nk0, uint32_t nk1) {
    extern __shared__ char raw[];
    const uint32_t rawu = smem_u32(raw);
    const uint32_t sbase = (rawu + 1023u) & ~1023u;

    const int tid = threadIdx.x;
    const int wid = tid >> 5;
    const int lid = tid & 31;
    const int wm  = wid >> 2;
    const int wn  = wid & 3;
    const int m0  = blockIdx.x * 128;
    const int n0  = blockIdx.y * 128;

    const int q = lid >> 3, r = lid & 7;
    const int rowA_l = r + (q & 1) * 8;
    const int kselA  = (q >> 1) * 16;
    const int rowB_l = r + (q >> 1) * 8;
    const int kselB  = (q & 1) * 16;

    float accS[2][4][4];
    float accB[2][4][4];
    #pragma unroll
    for (int a = 0; a < 2; ++a)
        #pragma unroll
        for (int b = 0; b < 4; ++b)
            #pragma unroll
            for (int e = 0; e < 4; ++e) { accS[a][b][e] = 0.f; accB[a][b][e] = 0.f; }

    const size_t a_tile = (size_t)(m0 >> 7) * nkc;
    const size_t b_tile = (size_t)(n0 >> 7) * nkc;
    const int total = nkc * 9;

    auto issue_stage = [&](int s) {
        int kc = s / 9, sub = s - kc * 9;
        uint32_t dst = sbase + (s % NSTAGE) * STAGE_STRIDE;
        const char* asrc = ab + ((a_tile + kc) * 9 + sub) * 32768;
        const char* bsrc = (sub < 8)
            ? swp + (((b_tile + kc) * 8) + sub) * 32768
            : bwp + (b_tile + kc) * 32768;
        #pragma unroll
        for (int rr = 0; rr < 4; ++rr) {
            uint32_t off = (uint32_t)(rr * THREADS + tid) * 16;
            CP_ASYNC16(dst + off, asrc + off);
        }
        #pragma unroll
        for (int rr = 0; rr < 4; ++rr) {
            uint32_t off = (uint32_t)(rr * THREADS + tid) * 16;
            CP_ASYNC16(dst + 32768 + off, bsrc + off);
        }
        CP_COMMIT();
    };

    auto do_mma = [&](int buf, float (&acc)[2][4][4]) {
        const uint32_t Ah = sbase + buf * STAGE_STRIDE;
        const uint32_t Al = Ah + 16384;
        const uint32_t Bh = Ah + 32768;
        const uint32_t Bl = Ah + 49152;
        #pragma unroll
        for (int k16 = 0; k16 < 4; ++k16) {
            const int kbyt = k16 * 32;
            uint32_t ah[2][4], al[2][4];
            #pragma unroll
            for (int mf = 0; mf < 2; ++mf) {
                int m = wm * 32 + mf * 16 + rowA_l;
                uint32_t off = (uint32_t)(m * 128)
                             + (((uint32_t)(kbyt + kselA)) ^ ((m * 16) & 0x70));
                LDSM4(ah[mf], Ah + off);
                LDSM4(al[mf], Al + off);
            }
            uint32_t bh[2][4], bl[2][4];
            #pragma unroll
            for (int nb = 0; nb < 2; ++nb) {
                int n = wn * 32 + nb * 16 + rowB_l;
                uint32_t off = (uint32_t)(n * 128)
                             + (((uint32_t)(kbyt + kselB)) ^ ((n * 16) & 0x70));
                LDSM4(bh[nb], Bh + off);
                LDSM4(bl[nb], Bl + off);
            }
            #pragma unroll
            for (int mf = 0; mf < 2; ++mf)
                #pragma unroll
                for (int nf = 0; nf < 4; ++nf) {
                    const int nb = nf >> 1, ri = (nf & 1) * 2;
                    MMA_BF16(acc[mf][nf], ah[mf], bh[nb][ri], bh[nb][ri + 1]);
                    MMA_BF16(acc[mf][nf], ah[mf], bl[nb][ri], bl[nb][ri + 1]);
                    MMA_BF16(acc[mf][nf], al[mf], bh[nb][ri], bh[nb][ri + 1]);
                }
        }
    };

    issue_stage(0);
    issue_stage(1);
    for (int s = 0; s < total; ++s) {
        if (s < total - 1) { CP_WAIT1(); } else { CP_WAIT0(); }
        __syncthreads();
        int sub = s % 9;
        if (sub == 8) do_mma(s % NSTAGE, accB);
        else          do_mma(s % NSTAGE, accS);
        if (s + 2 < total) issue_stage(s + 2);
    }

    // ---------------- epilogue ----------------
    const float snv = *snp;
    const int rq = lid >> 2, cq = (lid & 3) * 2;
    #pragma unroll
    for (int mf = 0; mf < 2; ++mf) {
        #pragma unroll
        for (int nf = 0; nf < 4; ++nf) {
            #pragma unroll
            for (int half = 0; half < 2; ++half) {
                int b = m0 + wm * 32 + mf * 16 + rq + half * 8;
                int obase = n0 + wn * 32 + nf * 8 + cq;
                float2 res;
                #pragma unroll
                for (int e = 0; e < 2; ++e) {
                    int o = obase + e;
                    float sv = accS[mf][nf][half * 2 + e];
                    float bv = accB[mf][nf][half * 2 + e];
                    float sg = 1.0f / (1.0f + __expf(-bv));
                    uint32_t li = (uint32_t)b * (uint32_t)O + (uint32_t)o;
                    uint32_t r0, r1;
                    threefry2x32_dev(nk0, nk1, 0u, li, r0, r1);
                    uint32_t bits = r0 ^ r1;
                    float f = __uint_as_float((bits >> 9) | 0x3f800000u) - 1.0f;
                    float uu = fmaxf(-0.99999994f, fmaf(f, 2.0f, -0.99999994f));
                    float nz = 1.41421356f * erfinvf(uu);
                    float val = bv * sg * sbp[o] + sv * ssp[o] + nz * snv;
                    if (e == 0) res.x = val; else res.y = val;
                }
                *reinterpret_cast<float2*>(&out[(size_t)b * O + obase]) = res;
            }
        }
    }
}

// ---------------- launch ----------------
extern "C" void kernel_launch(void* const* d_in, const int* in_sizes, int n_in,
                              void* d_out, int out_size) {
    const float* x = (const float*)d_in[0];
    const float* sw[4]; const float* bw[4]; const float* sb[4];
    const float* ss[4]; const float* sn[4];
    for (int li = 0; li < 4; ++li) {
        sw[li] = (const float*)d_in[1 + 5 * li + 0];
        bw[li] = (const float*)d_in[1 + 5 * li + 1];
        sb[li] = (const float*)d_in[1 + 5 * li + 2];
        ss[li] = (const float*)d_in[1 + 5 * li + 3];
        sn[li] = (const float*)d_in[1 + 5 * li + 4];
    }
    const int B = in_sizes[0] / 1024;   // 8192
    float* out  = (float*)d_out;
    float* xrec = out;
    float* z    = out + (size_t)B * 1024;

    float* h0; cudaGetSymbolAddress((void**)&h0, g_h0);
    float* h2; cudaGetSymbolAddress((void**)&h2, g_h2);
    char* swp; cudaGetSymbolAddress((void**)&swp, g_swp);
    char* bwp; cudaGetSymbolAddress((void**)&bwp, g_bwp);
    char* ab;  cudaGetSymbolAddress((void**)&ab, g_ab);

    const int Is[4] = {1024, 2048, 256, 2048};
    const int Os[4] = {2048, 256, 2048, 1024};
    size_t sw_off[4], bw_off[4];
    size_t so = 0, bo = 0;
    for (int li = 0; li < 4; ++li) {
        sw_off[li] = so; bw_off[li] = bo;
        so += (size_t)(Os[li] / 128) * (Is[li] / 64) * 8 * 32768;
        bo += (size_t)(Os[li] / 128) * (Is[li] / 64) * 32768;
    }

    uint32_t fk0[4], fk1[4];
    for (int li = 0; li < 4; ++li)
        threefry2x32_host(0u, 42u, 0u, (uint32_t)li, fk0[li], fk1[li]);

    cudaFuncSetAttribute(kan_mma_kernel,
                         cudaFuncAttributeMaxDynamicSharedMemorySize, SMEM_DYN);

    // pack weights (all layers, independent of activations)
    for (int li = 0; li < 4; ++li) {
        size_t tot = (size_t)Is[li] * Os[li] * 4;
        pack_sw_kernel<<<(unsigned)((tot + 255) / 256), 256>>>(
            sw[li], swp + sw_off[li], Is[li], Os[li]);
        size_t totb = (size_t)Os[li] * (Is[li] / 2);
        pack_bw_kernel<<<(unsigned)((totb + 255) / 256), 256>>>(
            bw[li], bwp + bw_off[li], Is[li], Os[li]);
    }

    dim3 blk(THREADS);
    const float* ins[4]  = {x, h0, z, h2};
    float* outs[4]       = {h0, z, h2, xrec};
    for (int li = 0; li < 4; ++li) {
        const int I = Is[li], O = Os[li];
        const int nkc = I / 64;
        const int mtiles = B / 128;
        // basis + x pack for this layer (depends on previous layer's output)
        pack_bases_kernel<<<(unsigned)(mtiles * nkc * 8), 256>>>(ins[li], ab, I, nkc);
        pack_x_kernel<<<(unsigned)(mtiles * nkc), 256>>>(ins[li], ab, I, nkc);
        dim3 g(mtiles, O / 128);
        kan_mma_kernel<<<g, blk, SMEM_DYN>>>(
            ab, swp + sw_off[li], bwp + bw_off[li],
            sb[li], ss[li], sn[li], outs[li],
            nkc, O, fk0[li], fk1[li]);
    }
}

// round 7
// speedup vs baseline: 3.6463x; 1.0019x over previous
#include <cuda_runtime.h>
#include <cuda_bf16.h>
#include <cstdint>
#include <cstddef>

#define THREADS 512

// Scratch activations (allocation-free)
__device__ float g_h0[8192u * 2048u];
__device__ float g_h2[8192u * 2048u];

// Packed pre-swizzled bf16 hi/lo weights:
// sw blocks: per (layer, ntile, kchunk64, sub): 32KB = [hi 16KB | lo 16KB]
// bw blocks: per (layer, ntile, kchunk64): 32KB
__device__ __align__(128) char g_swp[167772160];   // 160MB
__device__ __align__(128) char g_bwp[20971520];    // 20MB
// Packed pre-swizzled bf16 hi/lo A-blocks, reused per layer:
// per (mtile, kchunk64, sub 0..8): 32KB. sub 0..7 = basis tiles, sub 8 = x tile.
__device__ __align__(128) char g_ab[603979776];

// Gaussian basis recurrence: e_g = e0 * u^g * exp(-2e-4*g^2)
__constant__ float RAT[7] = {0.99980002f, 0.99940018f, 0.99900050f,
                             0.99860098f, 0.99820162f, 0.99780242f, 0.99740338f};

// ---------------- threefry2x32 (JAX-compatible, validated) ----------------
__device__ __forceinline__ uint32_t rotl32d(uint32_t v, int d) {
    return __funnelshift_l(v, v, d);
}
__device__ __forceinline__ void threefry2x32_dev(uint32_t k0, uint32_t k1,
                                                 uint32_t c0, uint32_t c1,
                                                 uint32_t& o0, uint32_t& o1) {
    uint32_t ks2 = k0 ^ k1 ^ 0x1BD11BDAu;
    uint32_t x0 = c0 + k0, x1 = c1 + k1;
#define TF_RND(r) { x0 += x1; x1 = rotl32d(x1, r); x1 ^= x0; }
    TF_RND(13) TF_RND(15) TF_RND(26) TF_RND(6)
    x0 += k1;  x1 += ks2 + 1u;
    TF_RND(17) TF_RND(29) TF_RND(16) TF_RND(24)
    x0 += ks2; x1 += k0 + 2u;
    TF_RND(13) TF_RND(15) TF_RND(26) TF_RND(6)
    x0 += k0;  x1 += k1 + 3u;
    TF_RND(17) TF_RND(29) TF_RND(16) TF_RND(24)
    x0 += k1;  x1 += ks2 + 4u;
    TF_RND(13) TF_RND(15) TF_RND(26) TF_RND(6)
    x0 += ks2; x1 += k0 + 5u;
#undef TF_RND
    o0 = x0; o1 = x1;
}
static inline uint32_t rotl32h(uint32_t v, int d) {
    return (v << d) | (v >> (32 - d));
}
static void threefry2x32_host(uint32_t k0, uint32_t k1, uint32_t c0, uint32_t c1,
                              uint32_t& o0, uint32_t& o1) {
    uint32_t ks2 = k0 ^ k1 ^ 0x1BD11BDAu;
    uint32_t x0 = c0 + k0, x1 = c1 + k1;
#define TF_RND(r) { x0 += x1; x1 = rotl32h(x1, r); x1 ^= x0; }
    TF_RND(13) TF_RND(15) TF_RND(26) TF_RND(6)
    x0 += k1;  x1 += ks2 + 1u;
    TF_RND(17) TF_RND(29) TF_RND(16) TF_RND(24)
    x0 += ks2; x1 += k0 + 2u;
    TF_RND(13) TF_RND(15) TF_RND(26) TF_RND(6)
    x0 += k0;  x1 += k1 + 3u;
    TF_RND(17) TF_RND(29) TF_RND(16) TF_RND(24)
    x0 += k1;  x1 += ks2 + 4u;
    TF_RND(13) TF_RND(15) TF_RND(26) TF_RND(6)
    x0 += ks2; x1 += k0 + 5u;
#undef TF_RND
    o0 = x0; o1 = x1;
}

// ---------------- helpers ----------------
__device__ __forceinline__ uint32_t smem_u32(const void* p) {
    uint32_t a;
    asm("{ .reg .u64 t; cvta.to.shared.u64 t, %1; cvt.u32.u64 %0, t; }"
        : "=r"(a) : "l"(p));
    return a;
}
#define SW128(o) ((o) ^ ((((uint32_t)(o)) >> 3) & 0x70))

#define LDSM4(rv, a) \
    asm volatile("ldmatrix.sync.aligned.m8n8.x4.shared.b16 {%0,%1,%2,%3}, [%4];" \
        : "=r"((rv)[0]), "=r"((rv)[1]), "=r"((rv)[2]), "=r"((rv)[3]) \
        : "r"(a))

#define MMA_BF16(c, a, b0, b1) \
    asm volatile("mma.sync.aligned.m16n8k16.row.col.f32.bf16.bf16.f32 " \
        "{%0,%1,%2,%3}, {%4,%5,%6,%7}, {%8,%9}, {%0,%1,%2,%3};" \
        : "+f"((c)[0]), "+f"((c)[1]), "+f"((c)[2]), "+f"((c)[3]) \
        : "r"((a)[0]), "r"((a)[1]), "r"((a)[2]), "r"((a)[3]), "r"(b0), "r"(b1))

#define CP_ASYNC16(dst, src) \
    asm volatile("cp.async.cg.shared.global [%0], [%1], 16;" \
                 :: "r"((uint32_t)(dst)), "l"(src) : "memory")
#define CP_COMMIT() asm volatile("cp.async.commit_group;" ::: "memory")
#define CP_WAIT0()  asm volatile("cp.async.wait_group 0;" ::: "memory")
#define CP_WAIT1()  asm volatile("cp.async.wait_group 1;" ::: "memory")

__device__ __forceinline__ void bfsplit2(float a, float b, uint32_t& hi2, uint32_t& lo2) {
    asm("cvt.rn.bf16x2.f32 %0, %1, %2;" : "=r"(hi2) : "f"(b), "f"(a));
    __nv_bfloat162 hv = *reinterpret_cast<__nv_bfloat162*>(&hi2);
    float ra = a - __bfloat162float(hv.x);
    float rb = b - __bfloat162float(hv.y);
    asm("cvt.rn.bf16x2.f32 %0, %1, %2;" : "=r"(lo2) : "f"(rb), "f"(ra));
}

// ---------------- pack kernels ----------------
__global__ void pack_sw_kernel(const float* __restrict__ sw, char* __restrict__ dst,
                               int I, int O) {
    size_t idx = (size_t)blockIdx.x * blockDim.x + threadIdx.x;
    size_t total = (size_t)I * O * 4;
    if (idx >= total) return;
    int g2 = (int)(idx & 3) * 2;
    size_t rem = idx >> 2;
    int o = (int)(rem % O);
    int i = (int)(rem / O);
    float2 wv = *reinterpret_cast<const float2*>(&sw[((size_t)i * O + o) * 8 + g2]);
    uint32_t hw, lw;
    bfsplit2(wv.x, wv.y, hw, lw);
    int t = o >> 7, n = o & 127, c = i >> 6, s = (i >> 3) & 7, ii = i & 7;
    size_t blk = (((size_t)t * (I >> 6) + c) * 8 + s) * 32768;
    uint32_t off = SW128((uint32_t)(n * 128 + (ii * 8 + g2) * 2));
    *reinterpret_cast<uint32_t*>(dst + blk + off) = hw;
    *reinterpret_cast<uint32_t*>(dst + blk + 16384 + off) = lw;
}

__global__ void pack_bw_kernel(const float* __restrict__ bw, char* __restrict__ dst,
                               int I, int O) {
    size_t idx = (size_t)blockIdx.x * blockDim.x + threadIdx.x;
    size_t total = (size_t)O * (I >> 1);
    if (idx >= total) return;
    int o = (int)(idx % O);
    int kp = (int)(idx / O);
    float b0 = bw[(size_t)(2 * kp) * O + o];
    float b1 = bw[(size_t)(2 * kp + 1) * O + o];
    uint32_t hw, lw;
    bfsplit2(b0, b1, hw, lw);
    int t = o >> 7, n = o & 127;
    int c = (2 * kp) >> 6, klocal = (2 * kp) & 63;
    size_t blk = ((size_t)t * (I >> 6) + c) * 32768;
    uint32_t off = SW128((uint32_t)(n * 128 + klocal * 2));
    *reinterpret_cast<uint32_t*>(dst + blk + off) = hw;
    *reinterpret_cast<uint32_t*>(dst + blk + 16384 + off) = lw;
}

// basis tiles: one block per (mtile, kchunk, sub); 256 threads, 4 tasks each
__global__ void pack_bases_kernel(const float* __restrict__ act,
                                  char* __restrict__ ab, int I, int nkc) {
    int bid = blockIdx.x;
    int sub = bid & 7;
    int t = bid >> 3;
    int kc = t % nkc;
    int mt = t / nkc;
    char* blk = ab + (((size_t)mt * nkc + kc) * 9 + sub) * 32768;
    int tid = threadIdx.x;
    #pragma unroll
    for (int rr = 0; rr < 4; ++rr) {
        int v = rr * 256 + tid;          // 1024 (mloc, il) tasks
        int mloc = v >> 3, il = v & 7;
        float xv = act[(size_t)(mt * 128 + mloc) * I + kc * 64 + sub * 8 + il];
        float d = xv + 0.044f;
        float e = __expf(-3.125f * d * d);
        float u = __expf(0.05f * d);
        float vv[8];
        vv[0] = e;
        #pragma unroll
        for (int g = 1; g < 8; ++g) vv[g] = vv[g - 1] * u * RAT[g - 1];
        uint32_t hw[4], lw[4];
        #pragma unroll
        for (int qq = 0; qq < 4; ++qq)
            bfsplit2(vv[2 * qq], vv[2 * qq + 1], hw[qq], lw[qq]);
        uint32_t off = SW128((uint32_t)(mloc * 128 + il * 16));
        *reinterpret_cast<uint4*>(blk + off) = make_uint4(hw[0], hw[1], hw[2], hw[3]);
        *reinterpret_cast<uint4*>(blk + 16384 + off) = make_uint4(lw[0], lw[1], lw[2], lw[3]);
    }
}

// x tiles (sub 8): one block per (mtile, kchunk); 256 threads, 8 tasks each
__global__ void pack_x_kernel(const float* __restrict__ act,
                              char* __restrict__ ab, int I, int nkc) {
    int bid = blockIdx.x;
    int kc = bid % nkc;
    int mt = bid / nkc;
    char* blk = ab + (((size_t)mt * nkc + kc) * 9 + 8) * 32768;
    int tid = threadIdx.x;
    #pragma unroll
    for (int rr = 0; rr < 8; ++rr) {
        int v = rr * 256 + tid;          // 2048 (mloc, c4) tasks
        int mloc = v >> 4, c4 = v & 15;
        float4 xv = *reinterpret_cast<const float4*>(
            &act[(size_t)(mt * 128 + mloc) * I + kc * 64 + c4 * 4]);
        uint32_t h0w, l0w, h1w, l1w;
        bfsplit2(xv.x, xv.y, h0w, l0w);
        bfsplit2(xv.z, xv.w, h1w, l1w);
        uint32_t off = SW128((uint32_t)(mloc * 128 + c4 * 8));
        *reinterpret_cast<uint2*>(blk + off) = make_uint2(h0w, h1w);
        *reinterpret_cast<uint2*>(blk + 16384 + off) = make_uint2(l0w, l1w);
    }
}

// ---------------- SMEM: 3-stage ring, 64KB per stage ----------------
static constexpr int STAGE_STRIDE = 65536;
static constexpr int NSTAGE = 3;
static constexpr int SMEM_SZ = NSTAGE * STAGE_STRIDE;   // 192KB
static constexpr int SMEM_DYN = SMEM_SZ + 1024;

// ---------------- main kernel: pure packed-GEMM pipeline ----------------
// grid: (ntiles, mtiles) — n FASTEST so concurrent CTAs share A-blocks in L2
__global__ __launch_bounds__(THREADS, 1)
void kan_mma_kernel(const char* __restrict__ ab,
                    const char* __restrict__ swp,
                    const char* __restrict__ bwp,
                    const float* __restrict__ sbp,
                    const float* __restrict__ ssp,
                    const float* __restrict__ snp,
                    float* __restrict__ out,
                    int nkc, int O,
                    uint32_t nk0, uint32_t nk1) {
    extern __shared__ char raw[];
    const uint32_t rawu = smem_u32(raw);
    const uint32_t sbase = (rawu + 1023u) & ~1023u;

    const int tid = threadIdx.x;
    const int wid = tid >> 5;
    const int lid = tid & 31;
    const int wm  = wid >> 2;
    const int wn  = wid & 3;
    const int m0  = blockIdx.y * 128;   // m slow
    const int n0  = blockIdx.x * 128;   // n fast

    const int q = lid >> 3, r = lid & 7;
    const int rowA_l = r + (q & 1) * 8;
    const int kselA  = (q >> 1) * 16;
    const int rowB_l = r + (q >> 1) * 8;
    const int kselB  = (q & 1) * 16;

    float accS[2][4][4];
    float accB[2][4][4];
    #pragma unroll
    for (int a = 0; a < 2; ++a)
        #pragma unroll
        for (int b = 0; b < 4; ++b)
            #pragma unroll
            for (int e = 0; e < 4; ++e) { accS[a][b][e] = 0.f; accB[a][b][e] = 0.f; }

    const size_t a_tile = (size_t)(m0 >> 7) * nkc;
    const size_t b_tile = (size_t)(n0 >> 7) * nkc;
    const int total = nkc * 9;

    auto issue_stage = [&](int s) {
        int kc = s / 9, sub = s - kc * 9;
        uint32_t dst = sbase + (s % NSTAGE) * STAGE_STRIDE;
        const char* asrc = ab + ((a_tile + kc) * 9 + sub) * 32768;
        const char* bsrc = (sub < 8)
            ? swp + (((b_tile + kc) * 8) + sub) * 32768
            : bwp + (b_tile + kc) * 32768;
        #pragma unroll
        for (int rr = 0; rr < 4; ++rr) {
            uint32_t off = (uint32_t)(rr * THREADS + tid) * 16;
            CP_ASYNC16(dst + off, asrc + off);
        }
        #pragma unroll
        for (int rr = 0; rr < 4; ++rr) {
            uint32_t off = (uint32_t)(rr * THREADS + tid) * 16;
            CP_ASYNC16(dst + 32768 + off, bsrc + off);
        }
        CP_COMMIT();
    };

    auto do_mma = [&](int buf, float (&acc)[2][4][4]) {
        const uint32_t Ah = sbase + buf * STAGE_STRIDE;
        const uint32_t Al = Ah + 16384;
        const uint32_t Bh = Ah + 32768;
        const uint32_t Bl = Ah + 49152;
        #pragma unroll
        for (int k16 = 0; k16 < 4; ++k16) {
            const int kbyt = k16 * 32;
            uint32_t ah[2][4], al[2][4];
            #pragma unroll
            for (int mf = 0; mf < 2; ++mf) {
                int m = wm * 32 + mf * 16 + rowA_l;
                uint32_t off = (uint32_t)(m * 128)
                             + (((uint32_t)(kbyt + kselA)) ^ ((m * 16) & 0x70));
                LDSM4(ah[mf], Ah + off);
                LDSM4(al[mf], Al + off);
            }
            uint32_t bh[2][4], bl[2][4];
            #pragma unroll
            for (int nb = 0; nb < 2; ++nb) {
                int n = wn * 32 + nb * 16 + rowB_l;
                uint32_t off = (uint32_t)(n * 128)
                             + (((uint32_t)(kbyt + kselB)) ^ ((n * 16) & 0x70));
                LDSM4(bh[nb], Bh + off);
                LDSM4(bl[nb], Bl + off);
            }
            #pragma unroll
            for (int mf = 0; mf < 2; ++mf)
                #pragma unroll
                for (int nf = 0; nf < 4; ++nf) {
                    const int nb = nf >> 1, ri = (nf & 1) * 2;
                    MMA_BF16(acc[mf][nf], ah[mf], bh[nb][ri], bh[nb][ri + 1]);
                    MMA_BF16(acc[mf][nf], ah[mf], bl[nb][ri], bl[nb][ri + 1]);
                    MMA_BF16(acc[mf][nf], al[mf], bh[nb][ri], bh[nb][ri + 1]);
                }
        }
    };

    issue_stage(0);
    issue_stage(1);
    for (int s = 0; s < total; ++s) {
        if (s < total - 1) { CP_WAIT1(); } else { CP_WAIT0(); }
        __syncthreads();
        int sub = s % 9;
        if (sub == 8) do_mma(s % NSTAGE, accB);
        else          do_mma(s % NSTAGE, accS);
        if (s + 2 < total) issue_stage(s + 2);
    }

    // ---------------- epilogue ----------------
    const float snv = *snp;
    const int rq = lid >> 2, cq = (lid & 3) * 2;
    #pragma unroll
    for (int mf = 0; mf < 2; ++mf) {
        #pragma unroll
        for (int nf = 0; nf < 4; ++nf) {
            #pragma unroll
            for (int half = 0; half < 2; ++half) {
                int b = m0 + wm * 32 + mf * 16 + rq + half * 8;
                int obase = n0 + wn * 32 + nf * 8 + cq;
                float2 res;
                #pragma unroll
                for (int e = 0; e < 2; ++e) {
                    int o = obase + e;
                    float sv = accS[mf][nf][half * 2 + e];
                    float bv = accB[mf][nf][half * 2 + e];
                    float sg = 1.0f / (1.0f + __expf(-bv));
                    uint32_t li = (uint32_t)b * (uint32_t)O + (uint32_t)o;
                    uint32_t r0, r1;
                    threefry2x32_dev(nk0, nk1, 0u, li, r0, r1);
                    uint32_t bits = r0 ^ r1;
                    float f = __uint_as_float((bits >> 9) | 0x3f800000u) - 1.0f;
                    float uu = fmaxf(-0.99999994f, fmaf(f, 2.0f, -0.99999994f));
                    float nz = 1.41421356f * erfinvf(uu);
                    float val = bv * sg * sbp[o] + sv * ssp[o] + nz * snv;
                    if (e == 0) res.x = val; else res.y = val;
                }
                *reinterpret_cast<float2*>(&out[(size_t)b * O + obase]) = res;
            }
        }
    }
}

// ---------------- launch ----------------
extern "C" void kernel_launch(void* const* d_in, const int* in_sizes, int n_in,
                              void* d_out, int out_size) {
    const float* x = (const float*)d_in[0];
    const float* sw[4]; const float* bw[4]; const float* sb[4];
    const float* ss[4]; const float* sn[4];
    for (int li = 0; li < 4; ++li) {
        sw[li] = (const float*)d_in[1 + 5 * li + 0];
        bw[li] = (const float*)d_in[1 + 5 * li + 1];
        sb[li] = (const float*)d_in[1 + 5 * li + 2];
        ss[li] = (const float*)d_in[1 + 5 * li + 3];
        sn[li] = (const float*)d_in[1 + 5 * li + 4];
    }
    const int B = in_sizes[0] / 1024;   // 8192
    float* out  = (float*)d_out;
    float* xrec = out;
    float* z    = out + (size_t)B * 1024;

    float* h0; cudaGetSymbolAddress((void**)&h0, g_h0);
    float* h2; cudaGetSymbolAddress((void**)&h2, g_h2);
    char* swp; cudaGetSymbolAddress((void**)&swp, g_swp);
    char* bwp; cudaGetSymbolAddress((void**)&bwp, g_bwp);
    char* ab;  cudaGetSymbolAddress((void**)&ab, g_ab);

    const int Is[4] = {1024, 2048, 256, 2048};
    const int Os[4] = {2048, 256, 2048, 1024};
    size_t sw_off[4], bw_off[4];
    size_t so = 0, bo = 0;
    for (int li = 0; li < 4; ++li) {
        sw_off[li] = so; bw_off[li] = bo;
        so += (size_t)(Os[li] / 128) * (Is[li] / 64) * 8 * 32768;
        bo += (size_t)(Os[li] / 128) * (Is[li] / 64) * 32768;
    }

    uint32_t fk0[4], fk1[4];
    for (int li = 0; li < 4; ++li)
        threefry2x32_host(0u, 42u, 0u, (uint32_t)li, fk0[li], fk1[li]);

    cudaFuncSetAttribute(kan_mma_kernel,
                         cudaFuncAttributeMaxDynamicSharedMemorySize, SMEM_DYN);

    // pack weights (all layers, independent of activations)
    for (int li = 0; li < 4; ++li) {
        size_t tot = (size_t)Is[li] * Os[li] * 4;
        pack_sw_kernel<<<(unsigned)((tot + 255) / 256), 256>>>(
            sw[li], swp + sw_off[li], Is[li], Os[li]);
        size_t totb = (size_t)Os[li] * (Is[li] / 2);
        pack_bw_kernel<<<(unsigned)((totb + 255) / 256), 256>>>(
            bw[li], bwp + bw_off[li], Is[li], Os[li]);
    }

    dim3 blk(THREADS);
    const float* ins[4]  = {x, h0, z, h2};
    float* outs[4]       = {h0, z, h2, xrec};
    for (int li = 0; li < 4; ++li) {
        const int I = Is[li], O = Os[li];
        const int nkc = I / 64;
        const int mtiles = B / 128;
        pack_bases_kernel<<<(unsigned)(mtiles * nkc * 8), 256>>>(ins[li], ab, I, nkc);
        pack_x_kernel<<<(unsigned)(mtiles * nkc), 256>>>(ins[li], ab, I, nkc);
        // n-tile fastest: concurrent CTAs share A-blocks (L2-resident)
        dim3 g(O / 128, mtiles);
        kan_mma_kernel<<<g, blk, SMEM_DYN>>>(
            ab, swp + sw_off[li], bwp + bw_off[li],
            sb[li], ss[li], sn[li], outs[li],
            nkc, O, fk0[li], fk1[li]);
    }
}